// round 14
// baseline (speedup 1.0000x reference)
#include <cuda_runtime.h>
#include <cuda_fp16.h>
#include <cstdint>
#include <math.h>

#define BATCH 4
#define SEQ   2048
#define EMB   1024
#define HEADS 16
#define HDIM  64
#define MROWS (BATCH*SEQ)   /* 8192 */
#define L2E   1.4426950408889634f

// Pair-permute within 16-half groups: pair p -> pos (p<4 ? 2p : 2(p-4)+1).
// Thread lc's two fragment pairs (lc, lc+4) land adjacent -> one LDS.64.

// Scratch (device globals: allocation-free per harness rules)
__device__ __align__(16) __half g_qk [(size_t)MROWS * 2 * EMB];          // q|k, d-permuted, q scaled by L2E/8
__device__ __align__(16) __half g_vt [(size_t)BATCH * HEADS * HDIM * SEQ]; // V^T, seq-permuted
__device__ __align__(16) __half g_att[(size_t)MROWS * EMB];              // attn out, k-permuted
__device__ __align__(16) __half g_xc [(size_t)MROWS * EMB];              // x, k-permuted
__device__ __align__(16) __half g_wqt[(size_t)3 * EMB * EMB];            // W_qkv^T, k-permuted
__device__ __align__(16) __half g_wot[(size_t)EMB * EMB];                // W_out^T, k-permuted

// ---------------------------------------------------------------------------
// helpers (portable PTX only)
// ---------------------------------------------------------------------------
__device__ __forceinline__ uint32_t smem_u32(const void* p) {
    uint32_t a;
    asm("{ .reg .u64 t; cvta.to.shared.u64 t, %1; cvt.u32.u64 %0, t; }" : "=r"(a) : "l"(p));
    return a;
}
__device__ __forceinline__ float fexp2(float x) {
    float y;
    asm("ex2.approx.f32 %0, %1;" : "=f"(y) : "f"(x));
    return y;
}
__device__ __forceinline__ void cp_async16(uint32_t dst, const void* src) {
    asm volatile("cp.async.cg.shared.global [%0], [%1], 16;" :: "r"(dst), "l"(src));
}
__device__ __forceinline__ void cp_commit() {
    asm volatile("cp.async.commit_group;" ::: "memory");
}
template <int N>
__device__ __forceinline__ void cp_wait() {
    asm volatile("cp.async.wait_group %0;" :: "n"(N) : "memory");
}
__device__ __forceinline__ void mma_f16(float& c0, float& c1, float& c2, float& c3,
                                        uint32_t a0, uint32_t a1, uint32_t a2, uint32_t a3,
                                        uint32_t b0, uint32_t b1) {
    asm volatile(
        "mma.sync.aligned.m16n8k16.row.col.f32.f16.f16.f32 "
        "{%0,%1,%2,%3}, {%4,%5,%6,%7}, {%8,%9}, {%0,%1,%2,%3};"
        : "+f"(c0), "+f"(c1), "+f"(c2), "+f"(c3)
        : "r"(a0), "r"(a1), "r"(a2), "r"(a3), "r"(b0), "r"(b1));
}
__device__ __forceinline__ int perm16h(int j) {   // half index j (0..15) -> permuted pos
    const int p = j >> 1;
    return ((p < 4) ? 4 * p : 4 * p - 14) + (j & 1);
}

// ---------------------------------------------------------------------------
// fp32 -> fp16, pair-permuted per 16-half group (one thread per group)
// ---------------------------------------------------------------------------
__global__ void convert_half_perm_kernel(const float* __restrict__ src,
                                         __half* __restrict__ dst, int ngroups) {
    int g = blockIdx.x * blockDim.x + threadIdx.x;
    if (g >= ngroups) return;
    const float* s = src + (size_t)g * 16;
    __half2 o[8];
    #pragma unroll
    for (int pp = 0; pp < 8; pp++) {
        const int p = (pp & 1) ? ((pp >> 1) + 4) : (pp >> 1);
        o[pp] = __floats2half2_rn(s[2 * p], s[2 * p + 1]);
    }
    *(uint4*)(dst + (size_t)g * 16)     = *(uint4*)(o);
    *(uint4*)(dst + (size_t)g * 16 + 8) = *(uint4*)(o + 4);
}

// ---------------------------------------------------------------------------
// transpose + fp16 + pair-permute: Wt[n][perm(k)] = h(W[k][n])
// ---------------------------------------------------------------------------
__global__ void transpose_half_perm_kernel(const float* __restrict__ W,
                                           __half* __restrict__ Wt, int K, int N) {
    __shared__ float t[32][33];
    const int n0 = blockIdx.x * 32, k0 = blockIdx.y * 32;
    const int x = threadIdx.x, y = threadIdx.y;  // 32 x 8
    #pragma unroll
    for (int i = 0; i < 4; i++)
        t[y + i * 8][x] = W[(size_t)(k0 + y + i * 8) * N + n0 + x];
    __syncthreads();
    const int px = (x & 16) + perm16h(x & 15);
    #pragma unroll
    for (int i = 0; i < 4; i++)
        Wt[(size_t)(n0 + y + i * 8) * K + k0 + px] = __float2half_rn(t[x][y + i * 8]);
}

// ---------------------------------------------------------------------------
// fp16 mma.sync GEMM: C[M,N] = A[M,K] @ Bt[N,K]^T + bias[N]
// CTA tile 64x128, 128 threads, 4 warps (2Mx2N), warp tile 32x64. BK=64,
// 3-stage cp.async, 3 CTAs/SM (smem 72KB, regs capped 170).
// GEMM1 grid 3072/444 slots -> ~7 waves (tail ~1% vs 15% at 128-row tiles).
// mode=1: q cols scaled by L2E/8; q,k d-permuted to g_qk; v transposed to g_vt
//         (epilogue staged in dead mainloop smem -> coalesced uint4 STGs).
// ---------------------------------------------------------------------------
#define BKH 64
#define ATILE_HALFS (4 * 64 * 16)      /* 4096 */
#define BTILE_HALFS (4 * 128 * 16)     /* 8192 */
#define STAGE_HALFS (ATILE_HALFS + BTILE_HALFS)
#define NSTAGE 3
#define GEMM_SMEM (NSTAGE * STAGE_HALFS * 2)   /* 73728 B */
#define ESR 136                        /* qk epilogue smem row stride (halfs) */
#define ESRV 72                        /* v  epilogue smem row stride (halfs) */

__global__ __launch_bounds__(128, 3)
void gemm_f16_kernel(const __half* __restrict__ A, const __half* __restrict__ Bt,
                     const float* __restrict__ bias, float* __restrict__ Cf,
                     int M, int N, int K, int mode)
{
    extern __shared__ __align__(16) __half sh[];

    const int tid  = threadIdx.x;
    const int wid  = tid >> 5;
    const int lane = tid & 31;
    const int wm   = (wid >> 1) * 32;   // 2 warps down M (64)
    const int wn   = (wid & 1) * 64;    // 2 warps across N (128)
    const int lr   = lane >> 2;
    const int lc   = lane & 3;
    const int n0   = blockIdx.x * 128;
    const int m0   = blockIdx.y * 64;
    const uint32_t smb = smem_u32(sh);

    float c[2][8][4];                   // [mt][nt][reg]
    #pragma unroll
    for (int i = 0; i < 2; i++)
        #pragma unroll
        for (int j = 0; j < 8; j++)
            #pragma unroll
            for (int r = 0; r < 4; r++) c[i][j][r] = 0.f;

    auto load_stage = [&](int ch, int s) {
        const __half* Ab = A  + (size_t)m0 * K + ch * BKH;
        const __half* Bb = Bt + (size_t)n0 * K + ch * BKH;
        const uint32_t sA = smb + (uint32_t)(s * STAGE_HALFS) * 2u;
        const uint32_t sB = sA + ATILE_HALFS * 2u;
        #pragma unroll
        for (int i = 0; i < 4; i++) {               // A: [4][64][16] = 512 cp16
            const int chk = i * 128 + tid;          // 0..511
            const int hh = chk & 1, row = (chk >> 1) & 63, ss = chk >> 7;
            cp_async16(sA + (uint32_t)(((ss * 64 + row) * 16 + hh * 8) * 2),
                       Ab + (size_t)row * K + ss * 16 + hh * 8);
        }
        #pragma unroll
        for (int i = 0; i < 8; i++) {               // B: [4][128][16] = 1024 cp16
            const int chk = i * 128 + tid;          // 0..1023
            const int hh = chk & 1, row = (chk >> 1) & 127, ss = chk >> 8;
            cp_async16(sB + (uint32_t)(((ss * 128 + row) * 16 + hh * 8) * 2),
                       Bb + (size_t)row * K + ss * 16 + hh * 8);
        }
    };

    const int NCH = K / BKH;

    load_stage(0, 0); cp_commit();
    load_stage(1, 1); cp_commit();

    for (int ch = 0; ch < NCH; ch++) {
        cp_wait<1>();
        __syncthreads();
        if (ch + 2 < NCH) load_stage(ch + 2, (ch + 2) % NSTAGE);
        cp_commit();

        const __half* As = sh + (ch % NSTAGE) * STAGE_HALFS;
        const __half* Bs = As + ATILE_HALFS;

        #pragma unroll
        for (int s = 0; s < 4; s++) {
            uint2 af[2][2];
            uint2 bf[8];
            #pragma unroll
            for (int mt = 0; mt < 2; mt++) {
                af[mt][0] = *(const uint2*)(As + ((s * 64 + wm + mt * 16 + lr) << 4) + 4 * lc);
                af[mt][1] = *(const uint2*)(As + ((s * 64 + wm + mt * 16 + lr + 8) << 4) + 4 * lc);
            }
            #pragma unroll
            for (int nt = 0; nt < 8; nt++)
                bf[nt] = *(const uint2*)(Bs + ((s * 128 + wn + nt * 8 + lr) << 4) + 4 * lc);
            #pragma unroll
            for (int mt = 0; mt < 2; mt++)
                #pragma unroll
                for (int nt = 0; nt < 8; nt++)
                    mma_f16(c[mt][nt][0], c[mt][nt][1], c[mt][nt][2], c[mt][nt][3],
                            af[mt][0].x, af[mt][1].x, af[mt][0].y, af[mt][1].y,
                            bf[nt].x, bf[nt].y);
        }
        __syncthreads();
    }
    // final barrier above -> mainloop smem is dead, reuse for epilogue staging

    if (mode == 1) {
        const int region = n0 >> 10;               // 0=q, 1=k, 2=v
        if (region < 2) {
            const float sc = (region == 0) ? (0.125f * L2E) : 1.0f;
            #pragma unroll
            for (int nt = 0; nt < 8; nt++) {
                const int col  = n0 + wn + nt * 8 + 2 * lc;
                const float b0v = bias[col], b1v = bias[col + 1];
                const int lcol = wn + nt * 8 + 2 * lc;
                const int scol = (lcol & ~15) + perm16h(lcol & 15);
                #pragma unroll
                for (int mt = 0; mt < 2; mt++) {
                    const int lrow = wm + mt * 16 + lr;
                    *(__half2*)&sh[lrow * ESR + scol] =
                        __floats2half2_rn((c[mt][nt][0] + b0v) * sc, (c[mt][nt][1] + b1v) * sc);
                    *(__half2*)&sh[(lrow + 8) * ESR + scol] =
                        __floats2half2_rn((c[mt][nt][2] + b0v) * sc, (c[mt][nt][3] + b1v) * sc);
                }
            }
            __syncthreads();
            const int cbase = (region == 1 ? 1024 : 0) + (n0 & 1023);
            #pragma unroll
            for (int it = 0; it < 8; it++) {
                const int id = it * 128 + tid;          // 0..1023
                const int lrow = id >> 4, cid = id & 15;
                *(uint4*)&g_qk[(size_t)(m0 + lrow) * 2048 + cbase + cid * 8] =
                    *(const uint4*)&sh[lrow * ESR + cid * 8];
            }
        } else {
            // v: stage transposed [col(d) 0..127][64 seq-permuted]
            #pragma unroll
            for (int nt = 0; nt < 8; nt++) {
                const int col  = n0 + wn + nt * 8 + 2 * lc;
                const float b0v = bias[col], b1v = bias[col + 1];
                const int lcol = wn + nt * 8 + 2 * lc;
                #pragma unroll
                for (int mt = 0; mt < 2; mt++) {
                    const int lrow = wm + mt * 16 + lr;
                    const int pr0 = (lrow & ~15) + perm16h(lrow & 15);
                    const int pr1 = (lrow & ~15) + perm16h((lrow & 15) + 8);
                    sh[lcol * ESRV + pr0]       = __float2half_rn(c[mt][nt][0] + b0v);
                    sh[(lcol + 1) * ESRV + pr0] = __float2half_rn(c[mt][nt][1] + b1v);
                    sh[lcol * ESRV + pr1]       = __float2half_rn(c[mt][nt][2] + b0v);
                    sh[(lcol + 1) * ESRV + pr1] = __float2half_rn(c[mt][nt][3] + b1v);
                }
            }
            __syncthreads();
            const int bb = m0 >> 11, seqb = m0 & 2047;
            #pragma unroll
            for (int it = 0; it < 8; it++) {
                const int id = it * 128 + tid;          // 0..1023
                const int lcol = id >> 3, cid = id & 7;
                const int d = (n0 - 2048) + lcol, hh = d >> 6, dd = d & 63;
                *(uint4*)&g_vt[((size_t)(bb * HEADS + hh) * 64 + dd) * 2048 + seqb + cid * 8] =
                    *(const uint4*)&sh[lcol * ESRV + cid * 8];
            }
        }
    } else {
        #pragma unroll
        for (int nt = 0; nt < 8; nt++) {
            const int col = n0 + wn + nt * 8 + 2 * lc;
            const float b0v = bias[col], b1v = bias[col + 1];
            #pragma unroll
            for (int mt = 0; mt < 2; mt++) {
                const size_t r0 = (size_t)(m0 + wm + mt * 16 + lr);
                *(float2*)(&Cf[r0 * N + col]) =
                    make_float2(c[mt][nt][0] + b0v, c[mt][nt][1] + b1v);
                *(float2*)(&Cf[(r0 + 8) * N + col]) =
                    make_float2(c[mt][nt][2] + b0v, c[mt][nt][3] + b1v);
            }
        }
    }
}

// ---------------------------------------------------------------------------
// Flash attention, fp16 mma.sync, 2 CTAs/SM, LPT order.
// Q pre-scaled by L2E/8 (GEMM1), slope scaled by L2E -> softmax is pure exp2.
// ---------------------------------------------------------------------------
#define QP_OFF 0
#define KS_OFF 8192
#define VT_OFF 24576
#define ATT_SMEM ((24576 + 16384) * 2)   /* 81920 B */

__global__ __launch_bounds__(256, 2)
void attn_f16_kernel(const __half* __restrict__ qk, const __half* __restrict__ vt,
                     __half* __restrict__ out)
{
    extern __shared__ __align__(16) __half sa[];

    const int tid  = threadIdx.x;
    const int wid  = tid >> 5;
    const int lane = tid & 31;
    const int lr   = lane >> 2;
    const int lc   = lane & 3;
    const int wm   = wid * 16;
    const int qt   = (gridDim.x - 1) - blockIdx.x;   // LPT: heavy tiles first
    const int h    = blockIdx.y;
    const int b    = blockIdx.z;
    const int q0   = qt * 128;
    const float slope = fexp2(-0.5f * (float)(h + 1)) * L2E;   // log2-units
    const uint32_t smb = smem_u32(sa);

    const __half* baseQ = qk + (size_t)b * SEQ * 2048 + h * 64;
    const __half* baseK = baseQ + 1024;
    const __half* baseV = vt + (size_t)(b * HEADS + h) * 64 * 2048;

    auto load_qk = [&](const __half* g, int row0, int soff) {   // [4][128][16]
        #pragma unroll
        for (int i = 0; i < 4; i++) {
            const int chk = i * 256 + tid;
            const int hh = chk & 1, row = (chk >> 1) & 127, ss = chk >> 8;
            cp_async16(smb + (uint32_t)((soff + (ss * 128 + row) * 16 + hh * 8) * 2),
                       g + (size_t)(row0 + row) * 2048 + ss * 16 + hh * 8);
        }
    };
    auto load_vt = [&](int kt, int soff) {                      // [8][64][16]
        #pragma unroll
        for (int i = 0; i < 4; i++) {
            const int chk = i * 256 + tid;
            const int hh = chk & 1, d = (chk >> 1) & 63, ss = chk >> 7;
            cp_async16(smb + (uint32_t)((soff + (ss * 64 + d) * 16 + hh * 8) * 2),
                       baseV + (size_t)d * 2048 + kt * 128 + ss * 16 + hh * 8);
        }
    };

    load_qk(baseQ, q0, QP_OFF);
    load_qk(baseK, 0, KS_OFF);
    load_vt(0, VT_OFF);
    cp_commit();

    uint2 qf[4][2];                      // Q fragments, hoisted at kt==0
    float m0 = -1e30f, m1 = -1e30f, l0 = 0.f, l1 = 0.f;
    float o[8][4];
    #pragma unroll
    for (int i = 0; i < 8; i++)
        #pragma unroll
        for (int r = 0; r < 4; r++) o[i][r] = 0.f;

    const int qrow0 = q0 + wm + lr;
    const int qrow1 = qrow0 + 8;

    for (int kt = 0; kt <= qt; kt++) {
        const int buf = kt & 1;
        if (kt < qt) {
            load_qk(baseK, (kt + 1) * 128, KS_OFF + (buf ^ 1) * 8192);
            load_vt(kt + 1, VT_OFF + (buf ^ 1) * 8192);
        }
        cp_commit();
        cp_wait<1>();
        __syncthreads();

        if (kt == 0) {                   // hoist Q fragments (own band only)
            #pragma unroll
            for (int s = 0; s < 4; s++) {
                qf[s][0] = *(const uint2*)(sa + QP_OFF + ((s * 128 + wm + lr) << 4) + 4 * lc);
                qf[s][1] = *(const uint2*)(sa + QP_OFF + ((s * 128 + wm + lr + 8) << 4) + 4 * lc);
            }
        }

        const __half* Ks = sa + KS_OFF + buf * 8192;
        const __half* Vs = sa + VT_OFF + buf * 8192;

        #pragma unroll
        for (int hf = 0; hf < 2; hf++) {
            // ---- S half: 128q x 64k (already in log2 units) ----
            float c[8][4];
            #pragma unroll
            for (int nt = 0; nt < 8; nt++)
                #pragma unroll
                for (int r = 0; r < 4; r++) c[nt][r] = 0.f;

            #pragma unroll
            for (int s = 0; s < 4; s++) {
                #pragma unroll
                for (int nt = 0; nt < 8; nt++) {
                    const uint2 kb2 = *(const uint2*)(Ks + ((s * 128 + hf * 64 + nt * 8 + lr) << 4) + 4 * lc);
                    mma_f16(c[nt][0], c[nt][1], c[nt][2], c[nt][3],
                            qf[s][0].x, qf[s][1].x, qf[s][0].y, qf[s][1].y,
                            kb2.x, kb2.y);
                }
            }

            // ---- ALiBi + (diagonal-only) mask + online softmax over 64 cols ----
            const int kb = kt * 128 + hf * 64 + 2 * lc;
            float al0 = slope * (float)(kb - qrow0);
            float al1 = slope * (float)(kb - qrow1);
            const float st8 = 8.f * slope;
            float mx0 = -1e30f, mx1 = -1e30f;
            #pragma unroll
            for (int nt = 0; nt < 8; nt++) {
                float s0 = c[nt][0] + al0;
                float s1 = c[nt][1] + al0 + slope;
                float s2 = c[nt][2] + al1;
                float s3 = c[nt][3] + al1 + slope;
                if (kt == qt) {
                    const int k0c = kb + nt * 8, k1c = k0c + 1;
                    if (k0c > qrow0) s0 = -1e30f;
                    if (k1c > qrow0) s1 = -1e30f;
                    if (k0c > qrow1) s2 = -1e30f;
                    if (k1c > qrow1) s3 = -1e30f;
                }
                c[nt][0] = s0; c[nt][1] = s1; c[nt][2] = s2; c[nt][3] = s3;
                mx0 = fmaxf(mx0, fmaxf(s0, s1));
                mx1 = fmaxf(mx1, fmaxf(s2, s3));
                al0 += st8; al1 += st8;
            }
            mx0 = fmaxf(mx0, __shfl_xor_sync(0xffffffffu, mx0, 1));
            mx0 = fmaxf(mx0, __shfl_xor_sync(0xffffffffu, mx0, 2));
            mx1 = fmaxf(mx1, __shfl_xor_sync(0xffffffffu, mx1, 1));
            mx1 = fmaxf(mx1, __shfl_xor_sync(0xffffffffu, mx1, 2));

            const float mn0 = fmaxf(m0, mx0), mn1 = fmaxf(m1, mx1);
            const float corr0 = fexp2(m0 - mn0);
            const float corr1 = fexp2(m1 - mn1);
            m0 = mn0; m1 = mn1;

            float ts0 = 0.f, ts1 = 0.f;
            __half* prow0 = sa + QP_OFF + (wm + lr) * 16 + 4 * lc;
            __half* prow1 = prow0 + 8 * 16;
            #pragma unroll
            for (int nt = 0; nt < 8; nt++) {
                const float e0 = fexp2(c[nt][0] - mn0);
                const float e1 = fexp2(c[nt][1] - mn0);
                const float e2 = fexp2(c[nt][2] - mn1);
                const float e3 = fexp2(c[nt][3] - mn1);
                ts0 += e0 + e1;
                ts1 += e2 + e3;
                const int po = (nt >> 1) * 2048 + 2 * (nt & 1);
                *(__half2*)(prow0 + po) = __floats2half2_rn(e0, e1);
                *(__half2*)(prow1 + po) = __floats2half2_rn(e2, e3);
            }
            ts0 += __shfl_xor_sync(0xffffffffu, ts0, 1);
            ts0 += __shfl_xor_sync(0xffffffffu, ts0, 2);
            ts1 += __shfl_xor_sync(0xffffffffu, ts1, 1);
            ts1 += __shfl_xor_sync(0xffffffffu, ts1, 2);
            l0 = l0 * corr0 + ts0;
            l1 = l1 * corr1 + ts1;
            #pragma unroll
            for (int i = 0; i < 8; i++) {
                o[i][0] *= corr0; o[i][1] *= corr0;
                o[i][2] *= corr1; o[i][3] *= corr1;
            }

            // ---- O += P_half @ V_half (own band; no barrier needed) ----
            #pragma unroll
            for (int s = 0; s < 4; s++) {
                const uint2 pa = *(const uint2*)(sa + QP_OFF + ((s * 128 + wm + lr) << 4) + 4 * lc);
                const uint2 pb = *(const uint2*)(sa + QP_OFF + ((s * 128 + wm + lr + 8) << 4) + 4 * lc);
                #pragma unroll
                for (int nt2 = 0; nt2 < 8; nt2++) {
                    const uint2 vb = *(const uint2*)(Vs + (((hf * 4 + s) * 64 + nt2 * 8 + lr) << 4) + 4 * lc);
                    mma_f16(o[nt2][0], o[nt2][1], o[nt2][2], o[nt2][3],
                            pa.x, pb.x, pa.y, pb.y, vb.x, vb.y);
                }
            }
        }
        __syncthreads();       // all reads of KS/VT[buf] done before reuse
    }

    // ---- epilogue: normalize, write k-permuted half2 (feeds GEMM2) ----
    const float inv0 = 1.f / l0, inv1 = 1.f / l1;
    __half* og = out + ((size_t)b * SEQ + qrow0) * 1024 + h * 64;
    #pragma unroll
    for (int nt2 = 0; nt2 < 8; nt2++) {
        const int col = nt2 * 8 + 2 * lc;                       // 0..63 within head
        const int cp2 = (col & ~15) + perm16h(col & 15);
        *(__half2*)(og + cp2) = __floats2half2_rn(o[nt2][0] * inv0, o[nt2][1] * inv0);
        *(__half2*)(og + 8 * 1024 + cp2) = __floats2half2_rn(o[nt2][2] * inv1, o[nt2][3] * inv1);
    }
}

// ---------------------------------------------------------------------------
extern "C" void kernel_launch(void* const* d_in, const int* in_sizes, int n_in,
                              void* d_out, int out_size)
{
    const float* x    = (const float*)d_in[0];
    // d_in[1] = mask (bool tril) — causality handled analytically
    const float* Wqkv = (const float*)d_in[2];
    const float* bqkv = (const float*)d_in[3];
    const float* Wout = (const float*)d_in[4];
    const float* bout = (const float*)d_in[5];
    float* out = (float*)d_out;

    __half *qk_p, *vt_p, *att_p, *xc_p, *wqt_p, *wot_p;
    cudaGetSymbolAddress((void**)&qk_p,  g_qk);
    cudaGetSymbolAddress((void**)&vt_p,  g_vt);
    cudaGetSymbolAddress((void**)&att_p, g_att);
    cudaGetSymbolAddress((void**)&xc_p,  g_xc);
    cudaGetSymbolAddress((void**)&wqt_p, g_wqt);
    cudaGetSymbolAddress((void**)&wot_p, g_wot);

    cudaFuncSetAttribute(gemm_f16_kernel,
                         cudaFuncAttributeMaxDynamicSharedMemorySize, GEMM_SMEM);
    cudaFuncSetAttribute(attn_f16_kernel,
                         cudaFuncAttributeMaxDynamicSharedMemorySize, ATT_SMEM);

    // 0) fp16 + pair-permute operands
    {
        const int ng = MROWS * EMB / 16;
        convert_half_perm_kernel<<<ng / 256, 256>>>(x, xc_p, ng);
    }
    transpose_half_perm_kernel<<<dim3(3 * EMB / 32, EMB / 32), dim3(32, 8)>>>(Wqkv, wqt_p, EMB, 3 * EMB);
    transpose_half_perm_kernel<<<dim3(EMB / 32, EMB / 32),     dim3(32, 8)>>>(Wout, wot_p, EMB, EMB);

    // 1) qkv = x @ W_qkv + b_qkv; q scaled by L2E/8 + d-permuted, k d-permuted,
    //    v transposed to g_vt
    gemm_f16_kernel<<<dim3(3 * EMB / 128, MROWS / 64), 128, GEMM_SMEM>>>(
        xc_p, wqt_p, bqkv, nullptr, MROWS, 3 * EMB, EMB, 1);

    // 2) attention (fp16 mma.sync, 2 CTAs/SM, LPT order, causal + ALiBi)
    attn_f16_kernel<<<dim3(SEQ / 128, HEADS, BATCH), 256, ATT_SMEM>>>(qk_p, vt_p, att_p);

    // 3) out = att @ W_out + b_out (fp32 natural output)
    gemm_f16_kernel<<<dim3(EMB / 128, MROWS / 64), 128, GEMM_SMEM>>>(
        att_p, wot_p, bout, out, MROWS, EMB, EMB, 0);
}

// round 15
// speedup vs baseline: 1.0741x; 1.0741x over previous
#include <cuda_runtime.h>
#include <cuda_fp16.h>
#include <cstdint>
#include <math.h>

#define BATCH 4
#define SEQ   2048
#define EMB   1024
#define HEADS 16
#define HDIM  64
#define MROWS (BATCH*SEQ)   /* 8192 */
#define L2E   1.4426950408889634f

// Pair-permute within 16-half groups: pair p -> pos (p<4 ? 2p : 2(p-4)+1).
// Thread lc's two fragment pairs (lc, lc+4) land adjacent -> one LDS.64.

// Scratch (device globals: allocation-free per harness rules)
__device__ __align__(16) __half g_qk [(size_t)MROWS * 2 * EMB];          // q|k, d-permuted, q scaled L2E/8
__device__ __align__(16) __half g_vt [(size_t)BATCH * HEADS * HDIM * SEQ]; // V^T, seq-permuted
__device__ __align__(16) __half g_att[(size_t)MROWS * EMB];              // attn out, k-permuted
__device__ __align__(16) __half g_xc [(size_t)MROWS * EMB];              // x, k-permuted
__device__ __align__(16) __half g_wqt[(size_t)3 * EMB * EMB];            // W_qkv^T, k-permuted
__device__ __align__(16) __half g_wot[(size_t)EMB * EMB];                // W_out^T, k-permuted

// ---------------------------------------------------------------------------
// helpers (portable PTX only)
// ---------------------------------------------------------------------------
__device__ __forceinline__ uint32_t smem_u32(const void* p) {
    uint32_t a;
    asm("{ .reg .u64 t; cvta.to.shared.u64 t, %1; cvt.u32.u64 %0, t; }" : "=r"(a) : "l"(p));
    return a;
}
__device__ __forceinline__ float fexp2(float x) {
    float y;
    asm("ex2.approx.f32 %0, %1;" : "=f"(y) : "f"(x));
    return y;
}
__device__ __forceinline__ void cp_async16(uint32_t dst, const void* src) {
    asm volatile("cp.async.cg.shared.global [%0], [%1], 16;" :: "r"(dst), "l"(src));
}
__device__ __forceinline__ void cp_commit() {
    asm volatile("cp.async.commit_group;" ::: "memory");
}
template <int N>
__device__ __forceinline__ void cp_wait() {
    asm volatile("cp.async.wait_group %0;" :: "n"(N) : "memory");
}
__device__ __forceinline__ void mma_f16(float& c0, float& c1, float& c2, float& c3,
                                        uint32_t a0, uint32_t a1, uint32_t a2, uint32_t a3,
                                        uint32_t b0, uint32_t b1) {
    asm volatile(
        "mma.sync.aligned.m16n8k16.row.col.f32.f16.f16.f32 "
        "{%0,%1,%2,%3}, {%4,%5,%6,%7}, {%8,%9}, {%0,%1,%2,%3};"
        : "+f"(c0), "+f"(c1), "+f"(c2), "+f"(c3)
        : "r"(a0), "r"(a1), "r"(a2), "r"(a3), "r"(b0), "r"(b1));
}
__device__ __forceinline__ int perm16h(int j) {   // half index j (0..15) -> permuted pos
    const int p = j >> 1;
    return ((p < 4) ? 4 * p : 4 * p - 14) + (j & 1);
}

// ---------------------------------------------------------------------------
// fp32 -> fp16, pair-permuted per 16-half group (one thread per group)
// ---------------------------------------------------------------------------
__global__ void convert_half_perm_kernel(const float* __restrict__ src,
                                         __half* __restrict__ dst, int ngroups) {
    int g = blockIdx.x * blockDim.x + threadIdx.x;
    if (g >= ngroups) return;
    const float* s = src + (size_t)g * 16;
    __half2 o[8];
    #pragma unroll
    for (int pp = 0; pp < 8; pp++) {
        const int p = (pp & 1) ? ((pp >> 1) + 4) : (pp >> 1);
        o[pp] = __floats2half2_rn(s[2 * p], s[2 * p + 1]);
    }
    *(uint4*)(dst + (size_t)g * 16)     = *(uint4*)(o);
    *(uint4*)(dst + (size_t)g * 16 + 8) = *(uint4*)(o + 4);
}

// ---------------------------------------------------------------------------
// transpose + fp16 + pair-permute: Wt[n][perm(k)] = h(W[k][n])
// ---------------------------------------------------------------------------
__global__ void transpose_half_perm_kernel(const float* __restrict__ W,
                                           __half* __restrict__ Wt, int K, int N) {
    __shared__ float t[32][33];
    const int n0 = blockIdx.x * 32, k0 = blockIdx.y * 32;
    const int x = threadIdx.x, y = threadIdx.y;  // 32 x 8
    #pragma unroll
    for (int i = 0; i < 4; i++)
        t[y + i * 8][x] = W[(size_t)(k0 + y + i * 8) * N + n0 + x];
    __syncthreads();
    const int px = (x & 16) + perm16h(x & 15);
    #pragma unroll
    for (int i = 0; i < 4; i++)
        Wt[(size_t)(n0 + y + i * 8) * K + k0 + px] = __float2half_rn(t[x][y + i * 8]);
}

// ---------------------------------------------------------------------------
// fp16 mma.sync GEMM (R13 geometry — empirical optimum: 128x128 CTA,
// 128 threads, 4 warps 2x2 of 64x64, BK=64, 3-stage, 2 CTAs/SM).
// mode=1 epilogue stages output in dead mainloop smem -> coalesced uint4 STGs;
// q scaled by L2E/8 (softmax in log2 units downstream).
// ---------------------------------------------------------------------------
#define BKH 64
#define TILE_HALFS (4 * 128 * 16)     /* 8192 */
#define STAGE_HALFS (2 * TILE_HALFS)
#define NSTAGE 3
#define GEMM_SMEM (NSTAGE * STAGE_HALFS * 2)   /* 98304 B */
#define ESR 136                        /* epilogue smem row stride (halfs) */

__global__ __launch_bounds__(128, 2)
void gemm_f16_kernel(const __half* __restrict__ A, const __half* __restrict__ Bt,
                     const float* __restrict__ bias, float* __restrict__ Cf,
                     int M, int N, int K, int mode)
{
    extern __shared__ __align__(16) __half sh[];

    const int tid  = threadIdx.x;
    const int wid  = tid >> 5;
    const int lane = tid & 31;
    const int wm   = (wid >> 1) * 64;
    const int wn   = (wid & 1) * 64;
    const int lr   = lane >> 2;
    const int lc   = lane & 3;
    const int n0   = blockIdx.x * 128;
    const int m0   = blockIdx.y * 128;
    const uint32_t smb = smem_u32(sh);

    float c[4][8][4];
    #pragma unroll
    for (int i = 0; i < 4; i++)
        #pragma unroll
        for (int j = 0; j < 8; j++)
            #pragma unroll
            for (int r = 0; r < 4; r++) c[i][j][r] = 0.f;

    auto load_stage = [&](int ch, int s) {
        const __half* Ab = A  + (size_t)m0 * K + ch * BKH;
        const __half* Bb = Bt + (size_t)n0 * K + ch * BKH;
        const uint32_t sA = smb + (uint32_t)(s * STAGE_HALFS) * 2u;
        const uint32_t sB = sA + TILE_HALFS * 2u;
        #pragma unroll
        for (int i = 0; i < 8; i++) {
            const int chk = i * 128 + tid;
            const int hh = chk & 1, row = (chk >> 1) & 127, ss = chk >> 8;
            const uint32_t off = (uint32_t)(((ss * 128 + row) * 16 + hh * 8) * 2);
            const size_t gofs = (size_t)row * K + ss * 16 + hh * 8;
            cp_async16(sA + off, Ab + gofs);
            cp_async16(sB + off, Bb + gofs);
        }
    };

    const int NCH = K / BKH;

    load_stage(0, 0); cp_commit();
    load_stage(1, 1); cp_commit();

    for (int ch = 0; ch < NCH; ch++) {
        cp_wait<1>();
        __syncthreads();
        if (ch + 2 < NCH) load_stage(ch + 2, (ch + 2) % NSTAGE);
        cp_commit();

        const __half* As = sh + (ch % NSTAGE) * STAGE_HALFS;
        const __half* Bs = As + TILE_HALFS;

        #pragma unroll
        for (int s = 0; s < 4; s++) {
            uint2 af[4][2];
            uint2 bf[8];
            #pragma unroll
            for (int mt = 0; mt < 4; mt++) {
                af[mt][0] = *(const uint2*)(As + ((s * 128 + wm + mt * 16 + lr) << 4) + 4 * lc);
                af[mt][1] = *(const uint2*)(As + ((s * 128 + wm + mt * 16 + lr + 8) << 4) + 4 * lc);
            }
            #pragma unroll
            for (int nt = 0; nt < 8; nt++)
                bf[nt] = *(const uint2*)(Bs + ((s * 128 + wn + nt * 8 + lr) << 4) + 4 * lc);
            #pragma unroll
            for (int mt = 0; mt < 4; mt++)
                #pragma unroll
                for (int nt = 0; nt < 8; nt++)
                    mma_f16(c[mt][nt][0], c[mt][nt][1], c[mt][nt][2], c[mt][nt][3],
                            af[mt][0].x, af[mt][1].x, af[mt][0].y, af[mt][1].y,
                            bf[nt].x, bf[nt].y);
        }
        __syncthreads();
    }
    // NOTE: final loop iteration ended with __syncthreads -> smem is free.

    if (mode == 1) {
        const int region = n0 >> 10;               // 0=q, 1=k, 2=v
        if (region < 2) {
            const float sc = (region == 0) ? (0.125f * L2E) : 1.0f;
            // stage [row][col d-permuted]
            #pragma unroll
            for (int nt = 0; nt < 8; nt++) {
                const int col  = n0 + wn + nt * 8 + 2 * lc;
                const float b0v = bias[col], b1v = bias[col + 1];
                const int lcol = wn + nt * 8 + 2 * lc;
                const int scol = (lcol & ~15) + perm16h(lcol & 15);
                #pragma unroll
                for (int mt = 0; mt < 4; mt++) {
                    const int lrow = wm + mt * 16 + lr;
                    *(__half2*)&sh[lrow * ESR + scol] =
                        __floats2half2_rn((c[mt][nt][0] + b0v) * sc, (c[mt][nt][1] + b1v) * sc);
                    *(__half2*)&sh[(lrow + 8) * ESR + scol] =
                        __floats2half2_rn((c[mt][nt][2] + b0v) * sc, (c[mt][nt][3] + b1v) * sc);
                }
            }
            __syncthreads();
            const int cbase = (region == 1 ? 1024 : 0) + (n0 & 1023);
            #pragma unroll
            for (int it = 0; it < 16; it++) {
                const int id = it * 128 + tid;
                const int lrow = id >> 4, cid = id & 15;
                *(uint4*)&g_qk[(size_t)(m0 + lrow) * 2048 + cbase + cid * 8] =
                    *(const uint4*)&sh[lrow * ESR + cid * 8];
            }
        } else {
            // v: stage transposed [col(d)][row seq-permuted]
            #pragma unroll
            for (int nt = 0; nt < 8; nt++) {
                const int col  = n0 + wn + nt * 8 + 2 * lc;
                const float b0v = bias[col], b1v = bias[col + 1];
                const int lcol = wn + nt * 8 + 2 * lc;
                #pragma unroll
                for (int mt = 0; mt < 4; mt++) {
                    const int lrow = wm + mt * 16 + lr;
                    const int pr0 = (lrow & ~15) + perm16h(lrow & 15);
                    const int pr1 = (lrow & ~15) + perm16h((lrow & 15) + 8);
                    sh[lcol * ESR + pr0]       = __float2half_rn(c[mt][nt][0] + b0v);
                    sh[(lcol + 1) * ESR + pr0] = __float2half_rn(c[mt][nt][1] + b1v);
                    sh[lcol * ESR + pr1]       = __float2half_rn(c[mt][nt][2] + b0v);
                    sh[(lcol + 1) * ESR + pr1] = __float2half_rn(c[mt][nt][3] + b1v);
                }
            }
            __syncthreads();
            const int bb = m0 >> 11, seqb = m0 & 2047;
            #pragma unroll
            for (int it = 0; it < 16; it++) {
                const int id = it * 128 + tid;
                const int lcol = id >> 4, cid = id & 15;
                const int d = (n0 - 2048) + lcol, hh = d >> 6, dd = d & 63;
                *(uint4*)&g_vt[((size_t)(bb * HEADS + hh) * 64 + dd) * 2048 + seqb + cid * 8] =
                    *(const uint4*)&sh[lcol * ESR + cid * 8];
            }
        }
    } else {
        #pragma unroll
        for (int nt = 0; nt < 8; nt++) {
            const int col = n0 + wn + nt * 8 + 2 * lc;
            const float b0v = bias[col], b1v = bias[col + 1];
            #pragma unroll
            for (int mt = 0; mt < 4; mt++) {
                const size_t r0 = (size_t)(m0 + wm + mt * 16 + lr);
                *(float2*)(&Cf[r0 * N + col]) =
                    make_float2(c[mt][nt][0] + b0v, c[mt][nt][1] + b1v);
                *(float2*)(&Cf[(r0 + 8) * N + col]) =
                    make_float2(c[mt][nt][2] + b0v, c[mt][nt][3] + b1v);
            }
        }
    }
}

// ---------------------------------------------------------------------------
// Flash attention, fp16 mma.sync, 2 CTAs/SM, LPT order.
// Q pre-scaled by L2E/8 (GEMM1), slope in log2 units -> softmax is pure exp2.
// ---------------------------------------------------------------------------
#define QP_OFF 0
#define KS_OFF 8192
#define VT_OFF 24576
#define ATT_SMEM ((24576 + 16384) * 2)   /* 81920 B */

__global__ __launch_bounds__(256, 2)
void attn_f16_kernel(const __half* __restrict__ qk, const __half* __restrict__ vt,
                     __half* __restrict__ out)
{
    extern __shared__ __align__(16) __half sa[];

    const int tid  = threadIdx.x;
    const int wid  = tid >> 5;
    const int lane = tid & 31;
    const int lr   = lane >> 2;
    const int lc   = lane & 3;
    const int wm   = wid * 16;
    const int qt   = (gridDim.x - 1) - blockIdx.x;   // LPT: heavy tiles first
    const int h    = blockIdx.y;
    const int b    = blockIdx.z;
    const int q0   = qt * 128;
    const float slope = fexp2(-0.5f * (float)(h + 1)) * L2E;   // log2-units
    const uint32_t smb = smem_u32(sa);

    const __half* baseQ = qk + (size_t)b * SEQ * 2048 + h * 64;
    const __half* baseK = baseQ + 1024;
    const __half* baseV = vt + (size_t)(b * HEADS + h) * 64 * 2048;

    auto load_qk = [&](const __half* g, int row0, int soff) {   // [4][128][16]
        #pragma unroll
        for (int i = 0; i < 4; i++) {
            const int chk = i * 256 + tid;
            const int hh = chk & 1, row = (chk >> 1) & 127, ss = chk >> 8;
            cp_async16(smb + (uint32_t)((soff + (ss * 128 + row) * 16 + hh * 8) * 2),
                       g + (size_t)(row0 + row) * 2048 + ss * 16 + hh * 8);
        }
    };
    auto load_vt = [&](int kt, int soff) {                      // [8][64][16]
        #pragma unroll
        for (int i = 0; i < 4; i++) {
            const int chk = i * 256 + tid;
            const int hh = chk & 1, d = (chk >> 1) & 63, ss = chk >> 7;
            cp_async16(smb + (uint32_t)((soff + (ss * 64 + d) * 16 + hh * 8) * 2),
                       baseV + (size_t)d * 2048 + kt * 128 + ss * 16 + hh * 8);
        }
    };

    load_qk(baseQ, q0, QP_OFF);
    load_qk(baseK, 0, KS_OFF);
    load_vt(0, VT_OFF);
    cp_commit();

    uint2 qf[4][2];                      // Q fragments, hoisted at kt==0
    float m0 = -1e30f, m1 = -1e30f, l0 = 0.f, l1 = 0.f;
    float o[8][4];
    #pragma unroll
    for (int i = 0; i < 8; i++)
        #pragma unroll
        for (int r = 0; r < 4; r++) o[i][r] = 0.f;

    const int qrow0 = q0 + wm + lr;
    const int qrow1 = qrow0 + 8;

    for (int kt = 0; kt <= qt; kt++) {
        const int buf = kt & 1;
        if (kt < qt) {
            load_qk(baseK, (kt + 1) * 128, KS_OFF + (buf ^ 1) * 8192);
            load_vt(kt + 1, VT_OFF + (buf ^ 1) * 8192);
        }
        cp_commit();
        cp_wait<1>();
        __syncthreads();

        if (kt == 0) {                   // hoist Q fragments (own band only)
            #pragma unroll
            for (int s = 0; s < 4; s++) {
                qf[s][0] = *(const uint2*)(sa + QP_OFF + ((s * 128 + wm + lr) << 4) + 4 * lc);
                qf[s][1] = *(const uint2*)(sa + QP_OFF + ((s * 128 + wm + lr + 8) << 4) + 4 * lc);
            }
        }

        const __half* Ks = sa + KS_OFF + buf * 8192;
        const __half* Vs = sa + VT_OFF + buf * 8192;

        #pragma unroll
        for (int hf = 0; hf < 2; hf++) {
            // ---- S half: 128q x 64k (log2 units) ----
            float c[8][4];
            #pragma unroll
            for (int nt = 0; nt < 8; nt++)
                #pragma unroll
                for (int r = 0; r < 4; r++) c[nt][r] = 0.f;

            #pragma unroll
            for (int s = 0; s < 4; s++) {
                #pragma unroll
                for (int nt = 0; nt < 8; nt++) {
                    const uint2 kb2 = *(const uint2*)(Ks + ((s * 128 + hf * 64 + nt * 8 + lr) << 4) + 4 * lc);
                    mma_f16(c[nt][0], c[nt][1], c[nt][2], c[nt][3],
                            qf[s][0].x, qf[s][1].x, qf[s][0].y, qf[s][1].y,
                            kb2.x, kb2.y);
                }
            }

            // ---- ALiBi + (diagonal-only) mask + online softmax over 64 cols ----
            const int kb = kt * 128 + hf * 64 + 2 * lc;
            float al0 = slope * (float)(kb - qrow0);
            float al1 = slope * (float)(kb - qrow1);
            const float st8 = 8.f * slope;
            float mx0 = -1e30f, mx1 = -1e30f;
            #pragma unroll
            for (int nt = 0; nt < 8; nt++) {
                float s0 = c[nt][0] + al0;
                float s1 = c[nt][1] + al0 + slope;
                float s2 = c[nt][2] + al1;
                float s3 = c[nt][3] + al1 + slope;
                if (kt == qt) {
                    const int k0c = kb + nt * 8, k1c = k0c + 1;
                    if (k0c > qrow0) s0 = -1e30f;
                    if (k1c > qrow0) s1 = -1e30f;
                    if (k0c > qrow1) s2 = -1e30f;
                    if (k1c > qrow1) s3 = -1e30f;
                }
                c[nt][0] = s0; c[nt][1] = s1; c[nt][2] = s2; c[nt][3] = s3;
                mx0 = fmaxf(mx0, fmaxf(s0, s1));
                mx1 = fmaxf(mx1, fmaxf(s2, s3));
                al0 += st8; al1 += st8;
            }
            mx0 = fmaxf(mx0, __shfl_xor_sync(0xffffffffu, mx0, 1));
            mx0 = fmaxf(mx0, __shfl_xor_sync(0xffffffffu, mx0, 2));
            mx1 = fmaxf(mx1, __shfl_xor_sync(0xffffffffu, mx1, 1));
            mx1 = fmaxf(mx1, __shfl_xor_sync(0xffffffffu, mx1, 2));

            const float mn0 = fmaxf(m0, mx0), mn1 = fmaxf(m1, mx1);
            const float corr0 = fexp2(m0 - mn0);
            const float corr1 = fexp2(m1 - mn1);
            m0 = mn0; m1 = mn1;

            float ts0 = 0.f, ts1 = 0.f;
            __half* prow0 = sa + QP_OFF + (wm + lr) * 16 + 4 * lc;
            __half* prow1 = prow0 + 8 * 16;
            #pragma unroll
            for (int nt = 0; nt < 8; nt++) {
                const float e0 = fexp2(c[nt][0] - mn0);
                const float e1 = fexp2(c[nt][1] - mn0);
                const float e2 = fexp2(c[nt][2] - mn1);
                const float e3 = fexp2(c[nt][3] - mn1);
                ts0 += e0 + e1;
                ts1 += e2 + e3;
                const int po = (nt >> 1) * 2048 + 2 * (nt & 1);
                *(__half2*)(prow0 + po) = __floats2half2_rn(e0, e1);
                *(__half2*)(prow1 + po) = __floats2half2_rn(e2, e3);
            }
            ts0 += __shfl_xor_sync(0xffffffffu, ts0, 1);
            ts0 += __shfl_xor_sync(0xffffffffu, ts0, 2);
            ts1 += __shfl_xor_sync(0xffffffffu, ts1, 1);
            ts1 += __shfl_xor_sync(0xffffffffu, ts1, 2);
            l0 = l0 * corr0 + ts0;
            l1 = l1 * corr1 + ts1;
            #pragma unroll
            for (int i = 0; i < 8; i++) {
                o[i][0] *= corr0; o[i][1] *= corr0;
                o[i][2] *= corr1; o[i][3] *= corr1;
            }

            // ---- O += P_half @ V_half (own band; no barrier needed) ----
            #pragma unroll
            for (int s = 0; s < 4; s++) {
                const uint2 pa = *(const uint2*)(sa + QP_OFF + ((s * 128 + wm + lr) << 4) + 4 * lc);
                const uint2 pb = *(const uint2*)(sa + QP_OFF + ((s * 128 + wm + lr + 8) << 4) + 4 * lc);
                #pragma unroll
                for (int nt2 = 0; nt2 < 8; nt2++) {
                    const uint2 vb = *(const uint2*)(Vs + (((hf * 4 + s) * 64 + nt2 * 8 + lr) << 4) + 4 * lc);
                    mma_f16(o[nt2][0], o[nt2][1], o[nt2][2], o[nt2][3],
                            pa.x, pb.x, pa.y, pb.y, vb.x, vb.y);
                }
            }
        }
        __syncthreads();       // all reads of KS/VT[buf] done before reuse
    }

    // ---- epilogue: normalize, write k-permuted half2 (feeds GEMM2) ----
    const float inv0 = 1.f / l0, inv1 = 1.f / l1;
    __half* og = out + ((size_t)b * SEQ + qrow0) * 1024 + h * 64;
    #pragma unroll
    for (int nt2 = 0; nt2 < 8; nt2++) {
        const int col = nt2 * 8 + 2 * lc;                       // 0..63 within head
        const int cp2 = (col & ~15) + perm16h(col & 15);
        *(__half2*)(og + cp2) = __floats2half2_rn(o[nt2][0] * inv0, o[nt2][1] * inv0);
        *(__half2*)(og + 8 * 1024 + cp2) = __floats2half2_rn(o[nt2][2] * inv1, o[nt2][3] * inv1);
    }
}

// ---------------------------------------------------------------------------
extern "C" void kernel_launch(void* const* d_in, const int* in_sizes, int n_in,
                              void* d_out, int out_size)
{
    const float* x    = (const float*)d_in[0];
    // d_in[1] = mask (bool tril) — causality handled analytically
    const float* Wqkv = (const float*)d_in[2];
    const float* bqkv = (const float*)d_in[3];
    const float* Wout = (const float*)d_in[4];
    const float* bout = (const float*)d_in[5];
    float* out = (float*)d_out;

    __half *qk_p, *vt_p, *att_p, *xc_p, *wqt_p, *wot_p;
    cudaGetSymbolAddress((void**)&qk_p,  g_qk);
    cudaGetSymbolAddress((void**)&vt_p,  g_vt);
    cudaGetSymbolAddress((void**)&att_p, g_att);
    cudaGetSymbolAddress((void**)&xc_p,  g_xc);
    cudaGetSymbolAddress((void**)&wqt_p, g_wqt);
    cudaGetSymbolAddress((void**)&wot_p, g_wot);

    cudaFuncSetAttribute(gemm_f16_kernel,
                         cudaFuncAttributeMaxDynamicSharedMemorySize, GEMM_SMEM);
    cudaFuncSetAttribute(attn_f16_kernel,
                         cudaFuncAttributeMaxDynamicSharedMemorySize, ATT_SMEM);

    // 0) fp16 + pair-permute operands
    {
        const int ng = MROWS * EMB / 16;
        convert_half_perm_kernel<<<ng / 256, 256>>>(x, xc_p, ng);
    }
    transpose_half_perm_kernel<<<dim3(3 * EMB / 32, EMB / 32), dim3(32, 8)>>>(Wqkv, wqt_p, EMB, 3 * EMB);
    transpose_half_perm_kernel<<<dim3(EMB / 32, EMB / 32),     dim3(32, 8)>>>(Wout, wot_p, EMB, EMB);

    // 1) qkv = x @ W_qkv + b_qkv; q scaled by L2E/8 + d-permuted, k d-permuted,
    //    v transposed to g_vt
    gemm_f16_kernel<<<dim3(3 * EMB / 128, MROWS / 128), 128, GEMM_SMEM>>>(
        xc_p, wqt_p, bqkv, nullptr, MROWS, 3 * EMB, EMB, 1);

    // 2) attention (fp16 mma.sync, 2 CTAs/SM, LPT order, causal + ALiBi)
    attn_f16_kernel<<<dim3(SEQ / 128, HEADS, BATCH), 256, ATT_SMEM>>>(qk_p, vt_p, att_p);

    // 3) out = att @ W_out + b_out (fp32 natural output)
    gemm_f16_kernel<<<dim3(EMB / 128, MROWS / 128), 128, GEMM_SMEM>>>(
        att_p, wot_p, bout, out, MROWS, EMB, EMB, 0);
}

// round 16
// speedup vs baseline: 1.1275x; 1.0497x over previous
#include <cuda_runtime.h>
#include <cuda_fp16.h>
#include <cstdint>
#include <math.h>

#define BATCH 4
#define SEQ   2048
#define EMB   1024
#define HEADS 16
#define HDIM  64
#define MROWS (BATCH*SEQ)   /* 8192 */
#define L2E   1.4426950408889634f

// Pair-permute within 16-half groups: pair p -> pos (p<4 ? 2p : 2(p-4)+1).
// Thread lc's two fragment pairs (lc, lc+4) land adjacent -> one LDS.64.

// Scratch (device globals: allocation-free per harness rules)
__device__ __align__(16) __half g_qk [(size_t)MROWS * 2 * EMB];          // q|k, d-permuted, q scaled L2E/8
__device__ __align__(16) __half g_vt [(size_t)BATCH * HEADS * HDIM * SEQ]; // V^T, seq-permuted
__device__ __align__(16) __half g_att[(size_t)MROWS * EMB];              // attn out, k-permuted
__device__ __align__(16) __half g_xc [(size_t)MROWS * EMB];              // x, k-permuted
__device__ __align__(16) __half g_wqt[(size_t)3 * EMB * EMB];            // W_qkv^T, k-permuted
__device__ __align__(16) __half g_wot[(size_t)EMB * EMB];                // W_out^T, k-permuted

template <bool B> struct BoolC { static constexpr bool value = B; };

// ---------------------------------------------------------------------------
// helpers (portable PTX only)
// ---------------------------------------------------------------------------
__device__ __forceinline__ uint32_t smem_u32(const void* p) {
    uint32_t a;
    asm("{ .reg .u64 t; cvta.to.shared.u64 t, %1; cvt.u32.u64 %0, t; }" : "=r"(a) : "l"(p));
    return a;
}
__device__ __forceinline__ float fexp2(float x) {
    float y;
    asm("ex2.approx.f32 %0, %1;" : "=f"(y) : "f"(x));
    return y;
}
__device__ __forceinline__ uint32_t h2exp2(uint32_t x) {
    uint32_t y;
    asm("ex2.approx.f16x2 %0, %1;" : "=r"(y) : "r"(x));
    return y;
}
__device__ __forceinline__ void cp_async16(uint32_t dst, const void* src) {
    asm volatile("cp.async.cg.shared.global [%0], [%1], 16;" :: "r"(dst), "l"(src));
}
__device__ __forceinline__ void cp_commit() {
    asm volatile("cp.async.commit_group;" ::: "memory");
}
template <int N>
__device__ __forceinline__ void cp_wait() {
    asm volatile("cp.async.wait_group %0;" :: "n"(N) : "memory");
}
__device__ __forceinline__ void mma_f16(float& c0, float& c1, float& c2, float& c3,
                                        uint32_t a0, uint32_t a1, uint32_t a2, uint32_t a3,
                                        uint32_t b0, uint32_t b1) {
    asm volatile(
        "mma.sync.aligned.m16n8k16.row.col.f32.f16.f16.f32 "
        "{%0,%1,%2,%3}, {%4,%5,%6,%7}, {%8,%9}, {%0,%1,%2,%3};"
        : "+f"(c0), "+f"(c1), "+f"(c2), "+f"(c3)
        : "r"(a0), "r"(a1), "r"(a2), "r"(a3), "r"(b0), "r"(b1));
}
__device__ __forceinline__ int perm16h(int j) {   // half index j (0..15) -> permuted pos
    const int p = j >> 1;
    return ((p < 4) ? 4 * p : 4 * p - 14) + (j & 1);
}

// ---------------------------------------------------------------------------
// fused prep: region-decoded single launch
//   blocks [0,2048):       x fp32 -> fp16 pair-permuted (g_xc)
//   blocks [2048,5120):    W_qkv transpose+half+perm   (g_wqt)
//   blocks [5120,6144):    W_out  transpose+half+perm  (g_wot)
// ---------------------------------------------------------------------------
__global__ __launch_bounds__(256)
void prep_kernel(const float* __restrict__ x,
                 const float* __restrict__ Wqkv,
                 const float* __restrict__ Wout,
                 __half* __restrict__ xc,
                 __half* __restrict__ wqt,
                 __half* __restrict__ wot)
{
    __shared__ float t[32][33];
    const int blk = blockIdx.x;
    const int tid = threadIdx.x;
    if (blk < 2048) {
        const int g = blk * 256 + tid;              // 16-half group id
        const float* s = x + (size_t)g * 16;
        __half2 o[8];
        #pragma unroll
        for (int pp = 0; pp < 8; pp++) {
            const int p = (pp & 1) ? ((pp >> 1) + 4) : (pp >> 1);
            o[pp] = __floats2half2_rn(s[2 * p], s[2 * p + 1]);
        }
        *(uint4*)(xc + (size_t)g * 16)     = *(uint4*)(o);
        *(uint4*)(xc + (size_t)g * 16 + 8) = *(uint4*)(o + 4);
    } else {
        const float* W; __half* Wt; int K, N, bx, by;
        if (blk < 2048 + 3072) {
            W = Wqkv; Wt = wqt; K = 1024; N = 3072;
            bx = (blk - 2048) % 96; by = (blk - 2048) / 96;
        } else {
            W = Wout; Wt = wot; K = 1024; N = 1024;
            bx = (blk - 5120) % 32; by = (blk - 5120) / 32;
        }
        const int n0 = bx * 32, k0 = by * 32;
        const int xx = tid & 31, yy = tid >> 5;     // 32 x 8
        #pragma unroll
        for (int i = 0; i < 4; i++)
            t[yy + i * 8][xx] = W[(size_t)(k0 + yy + i * 8) * N + n0 + xx];
        __syncthreads();
        const int px = (xx & 16) + perm16h(xx & 15);
        #pragma unroll
        for (int i = 0; i < 4; i++)
            Wt[(size_t)(n0 + yy + i * 8) * K + k0 + px] = __float2half_rn(t[xx][yy + i * 8]);
    }
}

// ---------------------------------------------------------------------------
// fp16 mma.sync GEMM (R13/R15 geometry — empirical optimum: 128x128 CTA,
// 128 threads, 4 warps 2x2 of 64x64, BK=64, 3-stage, 2 CTAs/SM).
// mode=1 epilogue stages output in dead mainloop smem -> coalesced uint4 STGs;
// q scaled by L2E/8 (softmax in log2 units downstream).
// ---------------------------------------------------------------------------
#define BKH 64
#define TILE_HALFS (4 * 128 * 16)     /* 8192 */
#define STAGE_HALFS (2 * TILE_HALFS)
#define NSTAGE 3
#define GEMM_SMEM (NSTAGE * STAGE_HALFS * 2)   /* 98304 B */
#define ESR 136                        /* epilogue smem row stride (halfs) */

__global__ __launch_bounds__(128, 2)
void gemm_f16_kernel(const __half* __restrict__ A, const __half* __restrict__ Bt,
                     const float* __restrict__ bias, float* __restrict__ Cf,
                     int M, int N, int K, int mode)
{
    extern __shared__ __align__(16) __half sh[];

    const int tid  = threadIdx.x;
    const int wid  = tid >> 5;
    const int lane = tid & 31;
    const int wm   = (wid >> 1) * 64;
    const int wn   = (wid & 1) * 64;
    const int lr   = lane >> 2;
    const int lc   = lane & 3;
    const int n0   = blockIdx.x * 128;
    const int m0   = blockIdx.y * 128;
    const uint32_t smb = smem_u32(sh);

    float c[4][8][4];
    #pragma unroll
    for (int i = 0; i < 4; i++)
        #pragma unroll
        for (int j = 0; j < 8; j++)
            #pragma unroll
            for (int r = 0; r < 4; r++) c[i][j][r] = 0.f;

    auto load_stage = [&](int ch, int s) {
        const __half* Ab = A  + (size_t)m0 * K + ch * BKH;
        const __half* Bb = Bt + (size_t)n0 * K + ch * BKH;
        const uint32_t sA = smb + (uint32_t)(s * STAGE_HALFS) * 2u;
        const uint32_t sB = sA + TILE_HALFS * 2u;
        #pragma unroll
        for (int i = 0; i < 8; i++) {
            const int chk = i * 128 + tid;
            const int hh = chk & 1, row = (chk >> 1) & 127, ss = chk >> 8;
            const uint32_t off = (uint32_t)(((ss * 128 + row) * 16 + hh * 8) * 2);
            const size_t gofs = (size_t)row * K + ss * 16 + hh * 8;
            cp_async16(sA + off, Ab + gofs);
            cp_async16(sB + off, Bb + gofs);
        }
    };

    const int NCH = K / BKH;

    load_stage(0, 0); cp_commit();
    load_stage(1, 1); cp_commit();

    for (int ch = 0; ch < NCH; ch++) {
        cp_wait<1>();
        __syncthreads();
        if (ch + 2 < NCH) load_stage(ch + 2, (ch + 2) % NSTAGE);
        cp_commit();

        const __half* As = sh + (ch % NSTAGE) * STAGE_HALFS;
        const __half* Bs = As + TILE_HALFS;

        #pragma unroll
        for (int s = 0; s < 4; s++) {
            uint2 af[4][2];
            uint2 bf[8];
            #pragma unroll
            for (int mt = 0; mt < 4; mt++) {
                af[mt][0] = *(const uint2*)(As + ((s * 128 + wm + mt * 16 + lr) << 4) + 4 * lc);
                af[mt][1] = *(const uint2*)(As + ((s * 128 + wm + mt * 16 + lr + 8) << 4) + 4 * lc);
            }
            #pragma unroll
            for (int nt = 0; nt < 8; nt++)
                bf[nt] = *(const uint2*)(Bs + ((s * 128 + wn + nt * 8 + lr) << 4) + 4 * lc);
            #pragma unroll
            for (int mt = 0; mt < 4; mt++)
                #pragma unroll
                for (int nt = 0; nt < 8; nt++)
                    mma_f16(c[mt][nt][0], c[mt][nt][1], c[mt][nt][2], c[mt][nt][3],
                            af[mt][0].x, af[mt][1].x, af[mt][0].y, af[mt][1].y,
                            bf[nt].x, bf[nt].y);
        }
        __syncthreads();
    }
    // NOTE: final loop iteration ended with __syncthreads -> smem is free.

    if (mode == 1) {
        const int region = n0 >> 10;               // 0=q, 1=k, 2=v
        if (region < 2) {
            const float sc = (region == 0) ? (0.125f * L2E) : 1.0f;
            // stage [row][col d-permuted]
            #pragma unroll
            for (int nt = 0; nt < 8; nt++) {
                const int col  = n0 + wn + nt * 8 + 2 * lc;
                const float b0v = bias[col], b1v = bias[col + 1];
                const int lcol = wn + nt * 8 + 2 * lc;
                const int scol = (lcol & ~15) + perm16h(lcol & 15);
                #pragma unroll
                for (int mt = 0; mt < 4; mt++) {
                    const int lrow = wm + mt * 16 + lr;
                    *(__half2*)&sh[lrow * ESR + scol] =
                        __floats2half2_rn((c[mt][nt][0] + b0v) * sc, (c[mt][nt][1] + b1v) * sc);
                    *(__half2*)&sh[(lrow + 8) * ESR + scol] =
                        __floats2half2_rn((c[mt][nt][2] + b0v) * sc, (c[mt][nt][3] + b1v) * sc);
                }
            }
            __syncthreads();
            const int cbase = (region == 1 ? 1024 : 0) + (n0 & 1023);
            #pragma unroll
            for (int it = 0; it < 16; it++) {
                const int id = it * 128 + tid;
                const int lrow = id >> 4, cid = id & 15;
                *(uint4*)&g_qk[(size_t)(m0 + lrow) * 2048 + cbase + cid * 8] =
                    *(const uint4*)&sh[lrow * ESR + cid * 8];
            }
        } else {
            // v: stage transposed [col(d)][row seq-permuted]
            #pragma unroll
            for (int nt = 0; nt < 8; nt++) {
                const int col  = n0 + wn + nt * 8 + 2 * lc;
                const float b0v = bias[col], b1v = bias[col + 1];
                const int lcol = wn + nt * 8 + 2 * lc;
                #pragma unroll
                for (int mt = 0; mt < 4; mt++) {
                    const int lrow = wm + mt * 16 + lr;
                    const int pr0 = (lrow & ~15) + perm16h(lrow & 15);
                    const int pr1 = (lrow & ~15) + perm16h((lrow & 15) + 8);
                    sh[lcol * ESR + pr0]       = __float2half_rn(c[mt][nt][0] + b0v);
                    sh[(lcol + 1) * ESR + pr0] = __float2half_rn(c[mt][nt][1] + b1v);
                    sh[lcol * ESR + pr1]       = __float2half_rn(c[mt][nt][2] + b0v);
                    sh[(lcol + 1) * ESR + pr1] = __float2half_rn(c[mt][nt][3] + b1v);
                }
            }
            __syncthreads();
            const int bb = m0 >> 11, seqb = m0 & 2047;
            #pragma unroll
            for (int it = 0; it < 16; it++) {
                const int id = it * 128 + tid;
                const int lcol = id >> 4, cid = id & 15;
                const int d = (n0 - 2048) + lcol, hh = d >> 6, dd = d & 63;
                *(uint4*)&g_vt[((size_t)(bb * HEADS + hh) * 64 + dd) * 2048 + seqb + cid * 8] =
                    *(const uint4*)&sh[lcol * ESR + cid * 8];
            }
        }
    } else {
        #pragma unroll
        for (int nt = 0; nt < 8; nt++) {
            const int col = n0 + wn + nt * 8 + 2 * lc;
            const float b0v = bias[col], b1v = bias[col + 1];
            #pragma unroll
            for (int mt = 0; mt < 4; mt++) {
                const size_t r0 = (size_t)(m0 + wm + mt * 16 + lr);
                *(float2*)(&Cf[r0 * N + col]) =
                    make_float2(c[mt][nt][0] + b0v, c[mt][nt][1] + b1v);
                *(float2*)(&Cf[(r0 + 8) * N + col]) =
                    make_float2(c[mt][nt][2] + b0v, c[mt][nt][3] + b1v);
            }
        }
    }
}

// ---------------------------------------------------------------------------
// Flash attention, fp16 mma.sync, 2 CTAs/SM, LPT order.
// Diagonal tile peeled (masking predicates only on the last tile);
// softmax uses ex2.approx.f16x2 (P is f16 anyway; normalization cancels
// the first-order exp error). Q pre-scaled by L2E/8; slope in log2 units.
// ---------------------------------------------------------------------------
#define QP_OFF 0
#define KS_OFF 8192
#define VT_OFF 24576
#define ATT_SMEM ((24576 + 16384) * 2)   /* 81920 B */

__global__ __launch_bounds__(256, 2)
void attn_f16_kernel(const __half* __restrict__ qk, const __half* __restrict__ vt,
                     __half* __restrict__ out)
{
    extern __shared__ __align__(16) __half sa[];

    const int tid  = threadIdx.x;
    const int wid  = tid >> 5;
    const int lane = tid & 31;
    const int lr   = lane >> 2;
    const int lc   = lane & 3;
    const int wm   = wid * 16;
    const int qt   = (gridDim.x - 1) - blockIdx.x;   // LPT: heavy tiles first
    const int h    = blockIdx.y;
    const int b    = blockIdx.z;
    const int q0   = qt * 128;
    const float slope = fexp2(-0.5f * (float)(h + 1)) * L2E;   // log2-units
    const uint32_t smb = smem_u32(sa);

    const __half* baseQ = qk + (size_t)b * SEQ * 2048 + h * 64;
    const __half* baseK = baseQ + 1024;
    const __half* baseV = vt + (size_t)(b * HEADS + h) * 64 * 2048;

    auto load_qk = [&](const __half* g, int row0, int soff) {   // [4][128][16]
        #pragma unroll
        for (int i = 0; i < 4; i++) {
            const int chk = i * 256 + tid;
            const int hh = chk & 1, row = (chk >> 1) & 127, ss = chk >> 8;
            cp_async16(smb + (uint32_t)((soff + (ss * 128 + row) * 16 + hh * 8) * 2),
                       g + (size_t)(row0 + row) * 2048 + ss * 16 + hh * 8);
        }
    };
    auto load_vt = [&](int kt, int soff) {                      // [8][64][16]
        #pragma unroll
        for (int i = 0; i < 4; i++) {
            const int chk = i * 256 + tid;
            const int hh = chk & 1, d = (chk >> 1) & 63, ss = chk >> 7;
            cp_async16(smb + (uint32_t)((soff + (ss * 64 + d) * 16 + hh * 8) * 2),
                       baseV + (size_t)d * 2048 + kt * 128 + ss * 16 + hh * 8);
        }
    };

    load_qk(baseQ, q0, QP_OFF);
    load_qk(baseK, 0, KS_OFF);
    load_vt(0, VT_OFF);
    cp_commit();

    uint2 qf[4][2];                      // Q fragments, hoisted at first tile
    float m0 = -1e30f, m1 = -1e30f, l0 = 0.f, l1 = 0.f;
    float o[8][4];
    #pragma unroll
    for (int i = 0; i < 8; i++)
        #pragma unroll
        for (int r = 0; r < 4; r++) o[i][r] = 0.f;

    const int qrow0 = q0 + wm + lr;
    const int qrow1 = qrow0 + 8;

    auto hoist_q = [&]() {
        #pragma unroll
        for (int s = 0; s < 4; s++) {
            qf[s][0] = *(const uint2*)(sa + QP_OFF + ((s * 128 + wm + lr) << 4) + 4 * lc);
            qf[s][1] = *(const uint2*)(sa + QP_OFF + ((s * 128 + wm + lr + 8) << 4) + 4 * lc);
        }
    };

    auto do_tile = [&](auto diagc, const int kt, const int buf) {
        constexpr bool DIAG = decltype(diagc)::value;
        const __half* Ks = sa + KS_OFF + buf * 8192;
        const __half* Vs = sa + VT_OFF + buf * 8192;

        #pragma unroll
        for (int hf = 0; hf < 2; hf++) {
            // ---- S half: 128q x 64k (log2 units) ----
            float c[8][4];
            #pragma unroll
            for (int nt = 0; nt < 8; nt++)
                #pragma unroll
                for (int r = 0; r < 4; r++) c[nt][r] = 0.f;

            #pragma unroll
            for (int s = 0; s < 4; s++) {
                #pragma unroll
                for (int nt = 0; nt < 8; nt++) {
                    const uint2 kb2 = *(const uint2*)(Ks + ((s * 128 + hf * 64 + nt * 8 + lr) << 4) + 4 * lc);
                    mma_f16(c[nt][0], c[nt][1], c[nt][2], c[nt][3],
                            qf[s][0].x, qf[s][1].x, qf[s][0].y, qf[s][1].y,
                            kb2.x, kb2.y);
                }
            }

            // ---- ALiBi (+ mask only on diagonal) + online softmax ----
            const int kb = kt * 128 + hf * 64 + 2 * lc;
            float al0 = slope * (float)(kb - qrow0);
            float al1 = slope * (float)(kb - qrow1);
            const float st8 = 8.f * slope;
            float mx0 = -1e30f, mx1 = -1e30f;
            #pragma unroll
            for (int nt = 0; nt < 8; nt++) {
                float s0 = c[nt][0] + al0;
                float s1 = c[nt][1] + al0 + slope;
                float s2 = c[nt][2] + al1;
                float s3 = c[nt][3] + al1 + slope;
                if (DIAG) {
                    const int k0c = kb + nt * 8, k1c = k0c + 1;
                    if (k0c > qrow0) s0 = -1e30f;
                    if (k1c > qrow0) s1 = -1e30f;
                    if (k0c > qrow1) s2 = -1e30f;
                    if (k1c > qrow1) s3 = -1e30f;
                }
                c[nt][0] = s0; c[nt][1] = s1; c[nt][2] = s2; c[nt][3] = s3;
                mx0 = fmaxf(mx0, fmaxf(s0, s1));
                mx1 = fmaxf(mx1, fmaxf(s2, s3));
                al0 += st8; al1 += st8;
            }
            mx0 = fmaxf(mx0, __shfl_xor_sync(0xffffffffu, mx0, 1));
            mx0 = fmaxf(mx0, __shfl_xor_sync(0xffffffffu, mx0, 2));
            mx1 = fmaxf(mx1, __shfl_xor_sync(0xffffffffu, mx1, 1));
            mx1 = fmaxf(mx1, __shfl_xor_sync(0xffffffffu, mx1, 2));

            const float mn0 = fmaxf(m0, mx0), mn1 = fmaxf(m1, mx1);
            const float corr0 = fexp2(m0 - mn0);
            const float corr1 = fexp2(m1 - mn1);
            m0 = mn0; m1 = mn1;

            float ts0 = 0.f, ts1 = 0.f;
            __half* prow0 = sa + QP_OFF + (wm + lr) * 16 + 4 * lc;
            __half* prow1 = prow0 + 8 * 16;
            #pragma unroll
            for (int nt = 0; nt < 8; nt++) {
                __half2 d0 = __floats2half2_rn(c[nt][0] - mn0, c[nt][1] - mn0);
                __half2 d1 = __floats2half2_rn(c[nt][2] - mn1, c[nt][3] - mn1);
                const uint32_t e0 = h2exp2(*(uint32_t*)&d0);
                const uint32_t e1 = h2exp2(*(uint32_t*)&d1);
                const int po = (nt >> 1) * 2048 + 2 * (nt & 1);
                *(uint32_t*)(prow0 + po) = e0;
                *(uint32_t*)(prow1 + po) = e1;
                const float2 f0 = __half22float2(*(const __half2*)&e0);
                const float2 f1 = __half22float2(*(const __half2*)&e1);
                ts0 += f0.x + f0.y;
                ts1 += f1.x + f1.y;
            }
            ts0 += __shfl_xor_sync(0xffffffffu, ts0, 1);
            ts0 += __shfl_xor_sync(0xffffffffu, ts0, 2);
            ts1 += __shfl_xor_sync(0xffffffffu, ts1, 1);
            ts1 += __shfl_xor_sync(0xffffffffu, ts1, 2);
            l0 = l0 * corr0 + ts0;
            l1 = l1 * corr1 + ts1;
            #pragma unroll
            for (int i = 0; i < 8; i++) {
                o[i][0] *= corr0; o[i][1] *= corr0;
                o[i][2] *= corr1; o[i][3] *= corr1;
            }

            // ---- O += P_half @ V_half (own band; no barrier needed) ----
            #pragma unroll
            for (int s = 0; s < 4; s++) {
                const uint2 pa = *(const uint2*)(sa + QP_OFF + ((s * 128 + wm + lr) << 4) + 4 * lc);
                const uint2 pb = *(const uint2*)(sa + QP_OFF + ((s * 128 + wm + lr + 8) << 4) + 4 * lc);
                #pragma unroll
                for (int nt2 = 0; nt2 < 8; nt2++) {
                    const uint2 vb = *(const uint2*)(Vs + (((hf * 4 + s) * 64 + nt2 * 8 + lr) << 4) + 4 * lc);
                    mma_f16(o[nt2][0], o[nt2][1], o[nt2][2], o[nt2][3],
                            pa.x, pb.x, pa.y, pb.y, vb.x, vb.y);
                }
            }
        }
    };

    // main tiles (no masking)
    for (int kt = 0; kt < qt; kt++) {
        const int buf = kt & 1;
        load_qk(baseK, (kt + 1) * 128, KS_OFF + (buf ^ 1) * 8192);
        load_vt(kt + 1, VT_OFF + (buf ^ 1) * 8192);
        cp_commit();
        cp_wait<1>();
        __syncthreads();
        if (kt == 0) hoist_q();
        do_tile(BoolC<false>{}, kt, buf);
        __syncthreads();       // all reads of KS/VT[buf] done before reuse
    }
    // diagonal tile (masked)
    {
        const int buf = qt & 1;
        cp_wait<0>();
        __syncthreads();
        if (qt == 0) hoist_q();
        do_tile(BoolC<true>{}, qt, buf);
    }

    // ---- epilogue: normalize, write k-permuted half2 (feeds GEMM2) ----
    const float inv0 = 1.f / l0, inv1 = 1.f / l1;
    __half* og = out + ((size_t)b * SEQ + qrow0) * 1024 + h * 64;
    #pragma unroll
    for (int nt2 = 0; nt2 < 8; nt2++) {
        const int col = nt2 * 8 + 2 * lc;                       // 0..63 within head
        const int cp2 = (col & ~15) + perm16h(col & 15);
        *(__half2*)(og + cp2) = __floats2half2_rn(o[nt2][0] * inv0, o[nt2][1] * inv0);
        *(__half2*)(og + 8 * 1024 + cp2) = __floats2half2_rn(o[nt2][2] * inv1, o[nt2][3] * inv1);
    }
}

// ---------------------------------------------------------------------------
extern "C" void kernel_launch(void* const* d_in, const int* in_sizes, int n_in,
                              void* d_out, int out_size)
{
    const float* x    = (const float*)d_in[0];
    // d_in[1] = mask (bool tril) — causality handled analytically
    const float* Wqkv = (const float*)d_in[2];
    const float* bqkv = (const float*)d_in[3];
    const float* Wout = (const float*)d_in[4];
    const float* bout = (const float*)d_in[5];
    float* out = (float*)d_out;

    __half *qk_p, *vt_p, *att_p, *xc_p, *wqt_p, *wot_p;
    cudaGetSymbolAddress((void**)&qk_p,  g_qk);
    cudaGetSymbolAddress((void**)&vt_p,  g_vt);
    cudaGetSymbolAddress((void**)&att_p, g_att);
    cudaGetSymbolAddress((void**)&xc_p,  g_xc);
    cudaGetSymbolAddress((void**)&wqt_p, g_wqt);
    cudaGetSymbolAddress((void**)&wot_p, g_wot);

    cudaFuncSetAttribute(gemm_f16_kernel,
                         cudaFuncAttributeMaxDynamicSharedMemorySize, GEMM_SMEM);
    cudaFuncSetAttribute(attn_f16_kernel,
                         cudaFuncAttributeMaxDynamicSharedMemorySize, ATT_SMEM);

    // 0) fused prep: x convert + both weight transposes (one launch)
    prep_kernel<<<6144, 256>>>(x, Wqkv, Wout, xc_p, wqt_p, wot_p);

    // 1) qkv = x @ W_qkv + b_qkv; q scaled by L2E/8 + d-permuted, k d-permuted,
    //    v transposed to g_vt
    gemm_f16_kernel<<<dim3(3 * EMB / 128, MROWS / 128), 128, GEMM_SMEM>>>(
        xc_p, wqt_p, bqkv, nullptr, MROWS, 3 * EMB, EMB, 1);

    // 2) attention (fp16 mma.sync, 2 CTAs/SM, LPT order, peeled diagonal)
    attn_f16_kernel<<<dim3(SEQ / 128, HEADS, BATCH), 256, ATT_SMEM>>>(qk_p, vt_p, att_p);

    // 3) out = att @ W_out + b_out (fp32 natural output)
    gemm_f16_kernel<<<dim3(EMB / 128, MROWS / 128), 128, GEMM_SMEM>>>(
        att_p, wot_p, bout, out, MROWS, EMB, EMB, 0);
}

// round 17
// speedup vs baseline: 1.2274x; 1.0886x over previous
#include <cuda_runtime.h>
#include <cuda_fp16.h>
#include <cstdint>
#include <math.h>

#define BATCH 4
#define SEQ   2048
#define EMB   1024
#define HEADS 16
#define HDIM  64
#define MROWS (BATCH*SEQ)   /* 8192 */
#define L2E   1.4426950408889634f

// Pair-permute within 16-half groups: pair p -> pos (p<4 ? 2p : 2(p-4)+1).
// Thread lc's two fragment pairs (lc, lc+4) land adjacent -> one LDS.64.

// Scratch (device globals: allocation-free per harness rules)
__device__ __align__(16) __half g_qk [(size_t)MROWS * 2 * EMB];          // q|k, d-permuted, q scaled L2E/8
__device__ __align__(16) __half g_vt [(size_t)BATCH * HEADS * HDIM * SEQ]; // V^T, seq-permuted
__device__ __align__(16) __half g_att[(size_t)MROWS * EMB];              // attn out, k-permuted
__device__ __align__(16) __half g_xc [(size_t)MROWS * EMB];              // x, k-permuted
__device__ __align__(16) __half g_wqt[(size_t)3 * EMB * EMB];            // W_qkv^T, k-permuted
__device__ __align__(16) __half g_wot[(size_t)EMB * EMB];                // W_out^T, k-permuted

template <bool B> struct BoolC { static constexpr bool value = B; };

// ---------------------------------------------------------------------------
// helpers (portable PTX only)
// ---------------------------------------------------------------------------
__device__ __forceinline__ uint32_t smem_u32(const void* p) {
    uint32_t a;
    asm("{ .reg .u64 t; cvta.to.shared.u64 t, %1; cvt.u32.u64 %0, t; }" : "=r"(a) : "l"(p));
    return a;
}
__device__ __forceinline__ float fexp2(float x) {
    float y;
    asm("ex2.approx.f32 %0, %1;" : "=f"(y) : "f"(x));
    return y;
}
__device__ __forceinline__ uint32_t h2exp2(uint32_t x) {
    uint32_t y;
    asm("ex2.approx.f16x2 %0, %1;" : "=r"(y) : "r"(x));
    return y;
}
__device__ __forceinline__ void cp_async16(uint32_t dst, const void* src) {
    asm volatile("cp.async.cg.shared.global [%0], [%1], 16;" :: "r"(dst), "l"(src));
}
__device__ __forceinline__ void cp_commit() {
    asm volatile("cp.async.commit_group;" ::: "memory");
}
template <int N>
__device__ __forceinline__ void cp_wait() {
    asm volatile("cp.async.wait_group %0;" :: "n"(N) : "memory");
}
__device__ __forceinline__ void mma_f16(float& c0, float& c1, float& c2, float& c3,
                                        uint32_t a0, uint32_t a1, uint32_t a2, uint32_t a3,
                                        uint32_t b0, uint32_t b1) {
    asm volatile(
        "mma.sync.aligned.m16n8k16.row.col.f32.f16.f16.f32 "
        "{%0,%1,%2,%3}, {%4,%5,%6,%7}, {%8,%9}, {%0,%1,%2,%3};"
        : "+f"(c0), "+f"(c1), "+f"(c2), "+f"(c3)
        : "r"(a0), "r"(a1), "r"(a2), "r"(a3), "r"(b0), "r"(b1));
}
__device__ __forceinline__ int perm16h(int j) {   // half index j (0..15) -> permuted pos
    const int p = j >> 1;
    return ((p < 4) ? 4 * p : 4 * p - 14) + (j & 1);
}

// ---------------------------------------------------------------------------
// fused prep: region-decoded single launch
//   blocks [0,2048):       x fp32 -> fp16 pair-permuted (g_xc)
//   blocks [2048,5120):    W_qkv transpose+half+perm   (g_wqt)
//   blocks [5120,6144):    W_out  transpose+half+perm  (g_wot)
// ---------------------------------------------------------------------------
__global__ __launch_bounds__(256)
void prep_kernel(const float* __restrict__ x,
                 const float* __restrict__ Wqkv,
                 const float* __restrict__ Wout,
                 __half* __restrict__ xc,
                 __half* __restrict__ wqt,
                 __half* __restrict__ wot)
{
    __shared__ float t[32][33];
    const int blk = blockIdx.x;
    const int tid = threadIdx.x;
    if (blk < 2048) {
        const int g = blk * 256 + tid;              // 16-half group id
        const float* s = x + (size_t)g * 16;
        __half2 o[8];
        #pragma unroll
        for (int pp = 0; pp < 8; pp++) {
            const int p = (pp & 1) ? ((pp >> 1) + 4) : (pp >> 1);
            o[pp] = __floats2half2_rn(s[2 * p], s[2 * p + 1]);
        }
        *(uint4*)(xc + (size_t)g * 16)     = *(uint4*)(o);
        *(uint4*)(xc + (size_t)g * 16 + 8) = *(uint4*)(o + 4);
    } else {
        const float* W; __half* Wt; int K, N, bx, by;
        if (blk < 2048 + 3072) {
            W = Wqkv; Wt = wqt; K = 1024; N = 3072;
            bx = (blk - 2048) % 96; by = (blk - 2048) / 96;
        } else {
            W = Wout; Wt = wot; K = 1024; N = 1024;
            bx = (blk - 5120) % 32; by = (blk - 5120) / 32;
        }
        const int n0 = bx * 32, k0 = by * 32;
        const int xx = tid & 31, yy = tid >> 5;     // 32 x 8
        #pragma unroll
        for (int i = 0; i < 4; i++)
            t[yy + i * 8][xx] = W[(size_t)(k0 + yy + i * 8) * N + n0 + xx];
        __syncthreads();
        const int px = (xx & 16) + perm16h(xx & 15);
        #pragma unroll
        for (int i = 0; i < 4; i++)
            Wt[(size_t)(n0 + yy + i * 8) * K + k0 + px] = __float2half_rn(t[xx][yy + i * 8]);
    }
}

// ---------------------------------------------------------------------------
// fp16 mma.sync GEMM (R13/R15 geometry). Single-barrier pipeline:
// per chunk: wait -> sync -> prefetch ch+2 -> compute. The former end-of-chunk
// barrier is redundant (top sync of chunk ch orders all warps' ch-1 reads
// before any overwrite of stage (ch-1)%3 by ch's prefetch).
// ---------------------------------------------------------------------------
#define BKH 64
#define TILE_HALFS (4 * 128 * 16)     /* 8192 */
#define STAGE_HALFS (2 * TILE_HALFS)
#define NSTAGE 3
#define GEMM_SMEM (NSTAGE * STAGE_HALFS * 2)   /* 98304 B */
#define ESR 136                        /* epilogue smem row stride (halfs) */

__global__ __launch_bounds__(128, 2)
void gemm_f16_kernel(const __half* __restrict__ A, const __half* __restrict__ Bt,
                     const float* __restrict__ bias, float* __restrict__ Cf,
                     int M, int N, int K, int mode)
{
    extern __shared__ __align__(16) __half sh[];

    const int tid  = threadIdx.x;
    const int wid  = tid >> 5;
    const int lane = tid & 31;
    const int wm   = (wid >> 1) * 64;
    const int wn   = (wid & 1) * 64;
    const int lr   = lane >> 2;
    const int lc   = lane & 3;
    const int n0   = blockIdx.x * 128;
    const int m0   = blockIdx.y * 128;
    const uint32_t smb = smem_u32(sh);

    float c[4][8][4];
    #pragma unroll
    for (int i = 0; i < 4; i++)
        #pragma unroll
        for (int j = 0; j < 8; j++)
            #pragma unroll
            for (int r = 0; r < 4; r++) c[i][j][r] = 0.f;

    auto load_stage = [&](int ch, int s) {
        const __half* Ab = A  + (size_t)m0 * K + ch * BKH;
        const __half* Bb = Bt + (size_t)n0 * K + ch * BKH;
        const uint32_t sA = smb + (uint32_t)(s * STAGE_HALFS) * 2u;
        const uint32_t sB = sA + TILE_HALFS * 2u;
        #pragma unroll
        for (int i = 0; i < 8; i++) {
            const int chk = i * 128 + tid;
            const int hh = chk & 1, row = (chk >> 1) & 127, ss = chk >> 8;
            const uint32_t off = (uint32_t)(((ss * 128 + row) * 16 + hh * 8) * 2);
            const size_t gofs = (size_t)row * K + ss * 16 + hh * 8;
            cp_async16(sA + off, Ab + gofs);
            cp_async16(sB + off, Bb + gofs);
        }
    };

    const int NCH = K / BKH;

    load_stage(0, 0); cp_commit();
    load_stage(1, 1); cp_commit();

    for (int ch = 0; ch < NCH; ch++) {
        cp_wait<1>();
        __syncthreads();
        if (ch + 2 < NCH) load_stage(ch + 2, (ch + 2) % NSTAGE);
        cp_commit();

        const __half* As = sh + (ch % NSTAGE) * STAGE_HALFS;
        const __half* Bs = As + TILE_HALFS;

        #pragma unroll
        for (int s = 0; s < 4; s++) {
            uint2 af[4][2];
            uint2 bf[8];
            #pragma unroll
            for (int mt = 0; mt < 4; mt++) {
                af[mt][0] = *(const uint2*)(As + ((s * 128 + wm + mt * 16 + lr) << 4) + 4 * lc);
                af[mt][1] = *(const uint2*)(As + ((s * 128 + wm + mt * 16 + lr + 8) << 4) + 4 * lc);
            }
            #pragma unroll
            for (int nt = 0; nt < 8; nt++)
                bf[nt] = *(const uint2*)(Bs + ((s * 128 + wn + nt * 8 + lr) << 4) + 4 * lc);
            #pragma unroll
            for (int mt = 0; mt < 4; mt++)
                #pragma unroll
                for (int nt = 0; nt < 8; nt++)
                    mma_f16(c[mt][nt][0], c[mt][nt][1], c[mt][nt][2], c[mt][nt][3],
                            af[mt][0].x, af[mt][1].x, af[mt][0].y, af[mt][1].y,
                            bf[nt].x, bf[nt].y);
        }
    }
    __syncthreads();   // all warps done with mainloop smem before epilogue reuse

    if (mode == 1) {
        const int region = n0 >> 10;               // 0=q, 1=k, 2=v
        if (region < 2) {
            const float sc = (region == 0) ? (0.125f * L2E) : 1.0f;
            // stage [row][col d-permuted]
            #pragma unroll
            for (int nt = 0; nt < 8; nt++) {
                const int col  = n0 + wn + nt * 8 + 2 * lc;
                const float b0v = bias[col], b1v = bias[col + 1];
                const int lcol = wn + nt * 8 + 2 * lc;
                const int scol = (lcol & ~15) + perm16h(lcol & 15);
                #pragma unroll
                for (int mt = 0; mt < 4; mt++) {
                    const int lrow = wm + mt * 16 + lr;
                    *(__half2*)&sh[lrow * ESR + scol] =
                        __floats2half2_rn((c[mt][nt][0] + b0v) * sc, (c[mt][nt][1] + b1v) * sc);
                    *(__half2*)&sh[(lrow + 8) * ESR + scol] =
                        __floats2half2_rn((c[mt][nt][2] + b0v) * sc, (c[mt][nt][3] + b1v) * sc);
                }
            }
            __syncthreads();
            const int cbase = (region == 1 ? 1024 : 0) + (n0 & 1023);
            #pragma unroll
            for (int it = 0; it < 16; it++) {
                const int id = it * 128 + tid;
                const int lrow = id >> 4, cid = id & 15;
                *(uint4*)&g_qk[(size_t)(m0 + lrow) * 2048 + cbase + cid * 8] =
                    *(const uint4*)&sh[lrow * ESR + cid * 8];
            }
        } else {
            // v: stage transposed [col(d)][row seq-permuted]
            #pragma unroll
            for (int nt = 0; nt < 8; nt++) {
                const int col  = n0 + wn + nt * 8 + 2 * lc;
                const float b0v = bias[col], b1v = bias[col + 1];
                const int lcol = wn + nt * 8 + 2 * lc;
                #pragma unroll
                for (int mt = 0; mt < 4; mt++) {
                    const int lrow = wm + mt * 16 + lr;
                    const int pr0 = (lrow & ~15) + perm16h(lrow & 15);
                    const int pr1 = (lrow & ~15) + perm16h((lrow & 15) + 8);
                    sh[lcol * ESR + pr0]       = __float2half_rn(c[mt][nt][0] + b0v);
                    sh[(lcol + 1) * ESR + pr0] = __float2half_rn(c[mt][nt][1] + b1v);
                    sh[lcol * ESR + pr1]       = __float2half_rn(c[mt][nt][2] + b0v);
                    sh[(lcol + 1) * ESR + pr1] = __float2half_rn(c[mt][nt][3] + b1v);
                }
            }
            __syncthreads();
            const int bb = m0 >> 11, seqb = m0 & 2047;
            #pragma unroll
            for (int it = 0; it < 16; it++) {
                const int id = it * 128 + tid;
                const int lcol = id >> 4, cid = id & 15;
                const int d = (n0 - 2048) + lcol, hh = d >> 6, dd = d & 63;
                *(uint4*)&g_vt[((size_t)(bb * HEADS + hh) * 64 + dd) * 2048 + seqb + cid * 8] =
                    *(const uint4*)&sh[lcol * ESR + cid * 8];
            }
        }
    } else {
        #pragma unroll
        for (int nt = 0; nt < 8; nt++) {
            const int col = n0 + wn + nt * 8 + 2 * lc;
            const float b0v = bias[col], b1v = bias[col + 1];
            #pragma unroll
            for (int mt = 0; mt < 4; mt++) {
                const size_t r0 = (size_t)(m0 + wm + mt * 16 + lr);
                *(float2*)(&Cf[r0 * N + col]) =
                    make_float2(c[mt][nt][0] + b0v, c[mt][nt][1] + b1v);
                *(float2*)(&Cf[(r0 + 8) * N + col]) =
                    make_float2(c[mt][nt][2] + b0v, c[mt][nt][3] + b1v);
            }
        }
    }
}

// ---------------------------------------------------------------------------
// Flash attention, fp16 mma.sync, 2 CTAs/SM.
// Single barrier per KV tile (wait -> sync -> prefetch -> compute).
// Diagonal tile peeled; warps 0-3 skip the fully-masked hf=1 half and
// warps 4-7 skip mask predicates on their fully-unmasked hf=0 half.
// True LPT: qt on gridDim.y reversed (all heavy CTAs launch first).
// ---------------------------------------------------------------------------
#define QP_OFF 0
#define KS_OFF 8192
#define VT_OFF 24576
#define ATT_SMEM ((24576 + 16384) * 2)   /* 81920 B */

__global__ __launch_bounds__(256, 2)
void attn_f16_kernel(const __half* __restrict__ qk, const __half* __restrict__ vt,
                     __half* __restrict__ out)
{
    extern __shared__ __align__(16) __half sa[];

    const int tid  = threadIdx.x;
    const int wid  = tid >> 5;
    const int lane = tid & 31;
    const int lr   = lane >> 2;
    const int lc   = lane & 3;
    const int wm   = wid * 16;
    const int qt   = (gridDim.y - 1) - blockIdx.y;   // LPT: heavy tiles first
    const int h    = blockIdx.x & 15;
    const int b    = blockIdx.x >> 4;
    const int q0   = qt * 128;
    const float slope = fexp2(-0.5f * (float)(h + 1)) * L2E;   // log2-units
    const uint32_t smb = smem_u32(sa);

    const __half* baseQ = qk + (size_t)b * SEQ * 2048 + h * 64;
    const __half* baseK = baseQ + 1024;
    const __half* baseV = vt + (size_t)(b * HEADS + h) * 64 * 2048;

    auto load_qk = [&](const __half* g, int row0, int soff) {   // [4][128][16]
        #pragma unroll
        for (int i = 0; i < 4; i++) {
            const int chk = i * 256 + tid;
            const int hh = chk & 1, row = (chk >> 1) & 127, ss = chk >> 8;
            cp_async16(smb + (uint32_t)((soff + (ss * 128 + row) * 16 + hh * 8) * 2),
                       g + (size_t)(row0 + row) * 2048 + ss * 16 + hh * 8);
        }
    };
    auto load_vt = [&](int kt, int soff) {                      // [8][64][16]
        #pragma unroll
        for (int i = 0; i < 4; i++) {
            const int chk = i * 256 + tid;
            const int hh = chk & 1, d = (chk >> 1) & 63, ss = chk >> 7;
            cp_async16(smb + (uint32_t)((soff + (ss * 64 + d) * 16 + hh * 8) * 2),
                       baseV + (size_t)d * 2048 + kt * 128 + ss * 16 + hh * 8);
        }
    };

    load_qk(baseQ, q0, QP_OFF);
    load_qk(baseK, 0, KS_OFF);
    load_vt(0, VT_OFF);
    cp_commit();

    uint2 qf[4][2];                      // Q fragments, hoisted at first tile
    float m0 = -1e30f, m1 = -1e30f, l0 = 0.f, l1 = 0.f;
    float o[8][4];
    #pragma unroll
    for (int i = 0; i < 8; i++)
        #pragma unroll
        for (int r = 0; r < 4; r++) o[i][r] = 0.f;

    const int qrow0 = q0 + wm + lr;
    const int qrow1 = qrow0 + 8;

    auto hoist_q = [&]() {
        #pragma unroll
        for (int s = 0; s < 4; s++) {
            qf[s][0] = *(const uint2*)(sa + QP_OFF + ((s * 128 + wm + lr) << 4) + 4 * lc);
            qf[s][1] = *(const uint2*)(sa + QP_OFF + ((s * 128 + wm + lr + 8) << 4) + 4 * lc);
        }
    };

    auto do_tile = [&](auto diagc, const int kt, const int buf) {
        constexpr bool DIAG = decltype(diagc)::value;
        const __half* Ks = sa + KS_OFF + buf * 8192;
        const __half* Vs = sa + VT_OFF + buf * 8192;

        #pragma unroll
        for (int hf = 0; hf < 2; hf++) {
            // diagonal: warps with rows < 64 are fully masked on hf=1 -> skip
            if (!(DIAG && hf == 1 && wm < 64)) {
                // ---- S half: 128q x 64k (log2 units) ----
                float c[8][4];
                #pragma unroll
                for (int nt = 0; nt < 8; nt++)
                    #pragma unroll
                    for (int r = 0; r < 4; r++) c[nt][r] = 0.f;

                #pragma unroll
                for (int s = 0; s < 4; s++) {
                    #pragma unroll
                    for (int nt = 0; nt < 8; nt++) {
                        const uint2 kb2 = *(const uint2*)(Ks + ((s * 128 + hf * 64 + nt * 8 + lr) << 4) + 4 * lc);
                        mma_f16(c[nt][0], c[nt][1], c[nt][2], c[nt][3],
                                qf[s][0].x, qf[s][1].x, qf[s][0].y, qf[s][1].y,
                                kb2.x, kb2.y);
                    }
                }

                // ---- ALiBi (+ mask only where needed) + online softmax ----
                const int kb = kt * 128 + hf * 64 + 2 * lc;
                const bool domask = DIAG && (hf == 1 || wm < 64);   // warp-uniform
                float al0 = slope * (float)(kb - qrow0);
                float al1 = slope * (float)(kb - qrow1);
                const float st8 = 8.f * slope;
                float mx0 = -1e30f, mx1 = -1e30f;
                #pragma unroll
                for (int nt = 0; nt < 8; nt++) {
                    float s0 = c[nt][0] + al0;
                    float s1 = c[nt][1] + al0 + slope;
                    float s2 = c[nt][2] + al1;
                    float s3 = c[nt][3] + al1 + slope;
                    if (domask) {
                        const int k0c = kb + nt * 8, k1c = k0c + 1;
                        if (k0c > qrow0) s0 = -1e30f;
                        if (k1c > qrow0) s1 = -1e30f;
                        if (k0c > qrow1) s2 = -1e30f;
                        if (k1c > qrow1) s3 = -1e30f;
                    }
                    c[nt][0] = s0; c[nt][1] = s1; c[nt][2] = s2; c[nt][3] = s3;
                    mx0 = fmaxf(mx0, fmaxf(s0, s1));
                    mx1 = fmaxf(mx1, fmaxf(s2, s3));
                    al0 += st8; al1 += st8;
                }
                mx0 = fmaxf(mx0, __shfl_xor_sync(0xffffffffu, mx0, 1));
                mx0 = fmaxf(mx0, __shfl_xor_sync(0xffffffffu, mx0, 2));
                mx1 = fmaxf(mx1, __shfl_xor_sync(0xffffffffu, mx1, 1));
                mx1 = fmaxf(mx1, __shfl_xor_sync(0xffffffffu, mx1, 2));

                const float mn0 = fmaxf(m0, mx0), mn1 = fmaxf(m1, mx1);
                const float corr0 = fexp2(m0 - mn0);
                const float corr1 = fexp2(m1 - mn1);
                m0 = mn0; m1 = mn1;

                float ts0 = 0.f, ts1 = 0.f;
                __half* prow0 = sa + QP_OFF + (wm + lr) * 16 + 4 * lc;
                __half* prow1 = prow0 + 8 * 16;
                #pragma unroll
                for (int nt = 0; nt < 8; nt++) {
                    __half2 d0 = __floats2half2_rn(c[nt][0] - mn0, c[nt][1] - mn0);
                    __half2 d1 = __floats2half2_rn(c[nt][2] - mn1, c[nt][3] - mn1);
                    const uint32_t e0 = h2exp2(*(uint32_t*)&d0);
                    const uint32_t e1 = h2exp2(*(uint32_t*)&d1);
                    const int po = (nt >> 1) * 2048 + 2 * (nt & 1);
                    *(uint32_t*)(prow0 + po) = e0;
                    *(uint32_t*)(prow1 + po) = e1;
                    const float2 f0 = __half22float2(*(const __half2*)&e0);
                    const float2 f1 = __half22float2(*(const __half2*)&e1);
                    ts0 += f0.x + f0.y;
                    ts1 += f1.x + f1.y;
                }
                ts0 += __shfl_xor_sync(0xffffffffu, ts0, 1);
                ts0 += __shfl_xor_sync(0xffffffffu, ts0, 2);
                ts1 += __shfl_xor_sync(0xffffffffu, ts1, 1);
                ts1 += __shfl_xor_sync(0xffffffffu, ts1, 2);
                l0 = l0 * corr0 + ts0;
                l1 = l1 * corr1 + ts1;
                #pragma unroll
                for (int i = 0; i < 8; i++) {
                    o[i][0] *= corr0; o[i][1] *= corr0;
                    o[i][2] *= corr1; o[i][3] *= corr1;
                }

                // ---- O += P_half @ V_half (own band; no barrier needed) ----
                #pragma unroll
                for (int s = 0; s < 4; s++) {
                    const uint2 pa = *(const uint2*)(sa + QP_OFF + ((s * 128 + wm + lr) << 4) + 4 * lc);
                    const uint2 pb = *(const uint2*)(sa + QP_OFF + ((s * 128 + wm + lr + 8) << 4) + 4 * lc);
                    #pragma unroll
                    for (int nt2 = 0; nt2 < 8; nt2++) {
                        const uint2 vb = *(const uint2*)(Vs + (((hf * 4 + s) * 64 + nt2 * 8 + lr) << 4) + 4 * lc);
                        mma_f16(o[nt2][0], o[nt2][1], o[nt2][2], o[nt2][3],
                                pa.x, pb.x, pa.y, pb.y, vb.x, vb.y);
                    }
                }
            }
        }
    };

    // main tiles (single barrier per tile: wait -> sync -> prefetch -> compute)
    for (int kt = 0; kt < qt; kt++) {
        const int buf = kt & 1;
        cp_wait<0>();
        __syncthreads();       // kt data visible to all; all warps done with buf^1
        load_qk(baseK, (kt + 1) * 128, KS_OFF + (buf ^ 1) * 8192);
        load_vt(kt + 1, VT_OFF + (buf ^ 1) * 8192);
        cp_commit();
        if (kt == 0) hoist_q();
        do_tile(BoolC<false>{}, kt, buf);
    }
    // diagonal tile (masked, warp-specialized)
    {
        const int buf = qt & 1;
        cp_wait<0>();
        __syncthreads();
        if (qt == 0) hoist_q();
        do_tile(BoolC<true>{}, qt, buf);
    }

    // ---- epilogue: normalize, write k-permuted half2 (feeds GEMM2) ----
    const float inv0 = 1.f / l0, inv1 = 1.f / l1;
    __half* og = out + ((size_t)b * SEQ + qrow0) * 1024 + h * 64;
    #pragma unroll
    for (int nt2 = 0; nt2 < 8; nt2++) {
        const int col = nt2 * 8 + 2 * lc;                       // 0..63 within head
        const int cp2 = (col & ~15) + perm16h(col & 15);
        *(__half2*)(og + cp2) = __floats2half2_rn(o[nt2][0] * inv0, o[nt2][1] * inv0);
        *(__half2*)(og + 8 * 1024 + cp2) = __floats2half2_rn(o[nt2][2] * inv1, o[nt2][3] * inv1);
    }
}

// ---------------------------------------------------------------------------
extern "C" void kernel_launch(void* const* d_in, const int* in_sizes, int n_in,
                              void* d_out, int out_size)
{
    const float* x    = (const float*)d_in[0];
    // d_in[1] = mask (bool tril) — causality handled analytically
    const float* Wqkv = (const float*)d_in[2];
    const float* bqkv = (const float*)d_in[3];
    const float* Wout = (const float*)d_in[4];
    const float* bout = (const float*)d_in[5];
    float* out = (float*)d_out;

    __half *qk_p, *vt_p, *att_p, *xc_p, *wqt_p, *wot_p;
    cudaGetSymbolAddress((void**)&qk_p,  g_qk);
    cudaGetSymbolAddress((void**)&vt_p,  g_vt);
    cudaGetSymbolAddress((void**)&att_p, g_att);
    cudaGetSymbolAddress((void**)&xc_p,  g_xc);
    cudaGetSymbolAddress((void**)&wqt_p, g_wqt);
    cudaGetSymbolAddress((void**)&wot_p, g_wot);

    cudaFuncSetAttribute(gemm_f16_kernel,
                         cudaFuncAttributeMaxDynamicSharedMemorySize, GEMM_SMEM);
    cudaFuncSetAttribute(attn_f16_kernel,
                         cudaFuncAttributeMaxDynamicSharedMemorySize, ATT_SMEM);

    // 0) fused prep: x convert + both weight transposes (one launch)
    prep_kernel<<<6144, 256>>>(x, Wqkv, Wout, xc_p, wqt_p, wot_p);

    // 1) qkv = x @ W_qkv + b_qkv; q scaled by L2E/8 + d-permuted, k d-permuted,
    //    v transposed to g_vt
    gemm_f16_kernel<<<dim3(3 * EMB / 128, MROWS / 128), 128, GEMM_SMEM>>>(
        xc_p, wqt_p, bqkv, nullptr, MROWS, 3 * EMB, EMB, 1);

    // 2) attention (fp16 mma.sync, 2 CTAs/SM, true-LPT grid, peeled diagonal)
    attn_f16_kernel<<<dim3(HEADS * BATCH, SEQ / 128), 256, ATT_SMEM>>>(qk_p, vt_p, att_p);

    // 3) out = att @ W_out + b_out (fp32 natural output)
    gemm_f16_kernel<<<dim3(EMB / 128, MROWS / 128), 128, GEMM_SMEM>>>(
        att_p, wot_p, bout, out, MROWS, EMB, EMB, 0);
}